// round 1
// baseline (speedup 1.0000x reference)
#include <cuda_runtime.h>
#include <cuda_bf16.h>
#include <math.h>

// ---------------------------------------------------------------------------
// MambaBlock: B=2, S=1024, D_MODEL=1024, D_INNER=2048, D_STATE=16, D_CONV=4
// TOK = B*S = 2048 tokens.
// Pipeline:
//  1) rmsnorm(x)                      -> g_xn   [2048,1024]
//  2) g_xn @ W_in                     -> g_xz   [2048,4096]  (x_inner | z)
//  3) causal depthwise conv + silu    -> g_xconv[2048,2048]
//  4) g_xconv @ W_xproj               -> g_ssm  [2048,33]    (dt_raw|B|C)
//  5) softplus(dt_raw*W_dt + b_dt)    -> g_dt   [2048,2048]
//  6) selective scan + gate silu(z)   -> g_y    [2048,2048]
//  7) x + g_y @ W_out                 -> d_out  [2048,1024]
// ---------------------------------------------------------------------------

#define TOK 2048
#define DM  1024
#define DI  2048
#define DS  16
#define NXP 33
#define SEQL 1024

__device__ float g_xn[TOK * DM];
__device__ float g_xz[TOK * 2 * DI];
__device__ float g_xconv[TOK * DI];
__device__ float g_ssm[TOK * NXP];
__device__ float g_WxT[NXP * DI];
__device__ float g_dt[TOK * DI];
__device__ float g_y[TOK * DI];

// ------------------------------ rmsnorm ------------------------------------
__global__ void __launch_bounds__(256) rmsnorm_kernel(
    const float* __restrict__ x, const float* __restrict__ w, float* __restrict__ xn)
{
    const int token = blockIdx.x;
    const int tid = threadIdx.x;
    const float4* x4 = reinterpret_cast<const float4*>(x + (size_t)token * DM);
    float4 v = x4[tid];
    float s = v.x * v.x + v.y * v.y + v.z * v.z + v.w * v.w;
    __shared__ float red[8];
    #pragma unroll
    for (int o = 16; o; o >>= 1) s += __shfl_xor_sync(0xffffffffu, s, o);
    if ((tid & 31) == 0) red[tid >> 5] = s;
    __syncthreads();
    if (tid < 32) {
        float t = (tid < 8) ? red[tid] : 0.f;
        #pragma unroll
        for (int o = 4; o; o >>= 1) t += __shfl_xor_sync(0xffffffffu, t, o);
        if (tid == 0) red[0] = t;
    }
    __syncthreads();
    const float ms = red[0] * (1.f / (float)DM);
    const float r = rsqrtf(ms + 1.1920928955078125e-07f);
    const float4* w4 = reinterpret_cast<const float4*>(w);
    float4 wv = w4[tid];
    float4 o;
    o.x = v.x * r * wv.x; o.y = v.y * r * wv.y;
    o.z = v.z * r * wv.z; o.w = v.w * r * wv.w;
    reinterpret_cast<float4*>(xn + (size_t)token * DM)[tid] = o;
}

// ------------------------------ SGEMM --------------------------------------
// C[M,N] = A[M,K] @ B[K,N]  (+ Rsd if RES).  All dims divisible by tiles.
template <bool RES>
__global__ void __launch_bounds__(256) sgemm_kernel(
    const float* __restrict__ A, const float* __restrict__ B,
    const float* __restrict__ Rsd, float* __restrict__ C,
    int M, int N, int K)
{
    constexpr int BM = 128, BN = 128, BK = 16, TM = 8, TN = 8;
    __shared__ float As[BK][BM];
    __shared__ float Bs[BK][BN + 4];
    const int tid = threadIdx.x;
    const int row0 = blockIdx.y * BM;
    const int col0 = blockIdx.x * BN;
    const int tx = tid & 15;
    const int ty = tid >> 4;

    float acc[TM][TN];
    #pragma unroll
    for (int i = 0; i < TM; i++)
        #pragma unroll
        for (int j = 0; j < TN; j++) acc[i][j] = 0.f;

    for (int kt = 0; kt < K; kt += BK) {
        #pragma unroll
        for (int it = 0; it < 2; ++it) {
            int s = tid + it * 256;
            int r = s >> 2;
            int kq = (s & 3) << 2;
            float4 v = *reinterpret_cast<const float4*>(&A[(size_t)(row0 + r) * K + kt + kq]);
            As[kq + 0][r] = v.x; As[kq + 1][r] = v.y;
            As[kq + 2][r] = v.z; As[kq + 3][r] = v.w;
        }
        #pragma unroll
        for (int it = 0; it < 2; ++it) {
            int s = tid + it * 256;
            int kr = s >> 5;
            int c4 = (s & 31) << 2;
            *reinterpret_cast<float4*>(&Bs[kr][c4]) =
                *reinterpret_cast<const float4*>(&B[(size_t)(kt + kr) * N + col0 + c4]);
        }
        __syncthreads();
        #pragma unroll
        for (int kk = 0; kk < BK; ++kk) {
            float a[TM], b[TN];
            #pragma unroll
            for (int i = 0; i < TM; i++) a[i] = As[kk][ty * TM + i];
            #pragma unroll
            for (int j = 0; j < TN; j++) b[j] = Bs[kk][tx * TN + j];
            #pragma unroll
            for (int i = 0; i < TM; i++)
                #pragma unroll
                for (int j = 0; j < TN; j++)
                    acc[i][j] = fmaf(a[i], b[j], acc[i][j]);
        }
        __syncthreads();
    }

    #pragma unroll
    for (int i = 0; i < TM; i++) {
        const int r = row0 + ty * TM + i;
        #pragma unroll
        for (int j = 0; j < TN; j += 4) {
            const int c = col0 + tx * TN + j;
            float4 v;
            v.x = acc[i][j + 0]; v.y = acc[i][j + 1];
            v.z = acc[i][j + 2]; v.w = acc[i][j + 3];
            if (RES) {
                float4 rr = *reinterpret_cast<const float4*>(&Rsd[(size_t)r * N + c]);
                v.x += rr.x; v.y += rr.y; v.z += rr.z; v.w += rr.w;
            }
            *reinterpret_cast<float4*>(&C[(size_t)r * N + c]) = v;
        }
    }
}

// ---------------------- causal depthwise conv + silu -----------------------
__global__ void __launch_bounds__(256) conv_silu_kernel(
    const float* __restrict__ xz, const float* __restrict__ cw,
    const float* __restrict__ cb, float* __restrict__ xconv)
{
    const int idx = blockIdx.x * 256 + threadIdx.x;   // TOK*DI threads
    const int ch = idx & (DI - 1);
    const int token = idx >> 11;
    const int t = token & (SEQL - 1);
    const int b = token >> 10;
    float acc = cb[ch];
    const float* base = xz + (size_t)(b * SEQL) * (2 * DI) + ch;
    #pragma unroll
    for (int k = 0; k < 4; ++k) {
        const int tt = t - 3 + k;
        if (tt >= 0)
            acc = fmaf(base[(size_t)tt * (2 * DI)], cw[ch * 4 + k], acc);
    }
    xconv[idx] = acc / (1.f + __expf(-acc));   // silu
}

// ------------------------ W_xproj transpose --------------------------------
__global__ void wxt_kernel(const float* __restrict__ W, float* __restrict__ WT)
{
    const int idx = blockIdx.x * 256 + threadIdx.x;
    if (idx < DI * NXP) {
        const int k = idx / NXP;
        const int c = idx - k * NXP;
        WT[c * DI + k] = W[idx];
    }
}

// ----------------------------- xproj ---------------------------------------
// ssm[token, c] = sum_k xconv[token,k] * WxT[c,k]; warp per token.
__global__ void __launch_bounds__(256) xproj_kernel(
    const float* __restrict__ xconv, const float* __restrict__ WxT,
    float* __restrict__ ssm)
{
    const int warp = threadIdx.x >> 5;
    const int lane = threadIdx.x & 31;
    const int token = blockIdx.x * 8 + warp;
    const float4* x4 = reinterpret_cast<const float4*>(xconv + (size_t)token * DI);
    for (int c = 0; c < NXP; ++c) {
        const float4* w4 = reinterpret_cast<const float4*>(WxT + (size_t)c * DI);
        float acc = 0.f;
        for (int i = lane; i < DI / 4; i += 32) {
            float4 a = x4[i];
            float4 w = w4[i];
            acc = fmaf(a.x, w.x, acc);
            acc = fmaf(a.y, w.y, acc);
            acc = fmaf(a.z, w.z, acc);
            acc = fmaf(a.w, w.w, acc);
        }
        #pragma unroll
        for (int o = 16; o; o >>= 1) acc += __shfl_xor_sync(0xffffffffu, acc, o);
        if (lane == 0) ssm[token * NXP + c] = acc;
    }
}

// ----------------------------- dt = softplus --------------------------------
__global__ void __launch_bounds__(256) dt_kernel(
    const float* __restrict__ ssm, const float* __restrict__ W_dt,
    const float* __restrict__ b_dt, float* __restrict__ dtout)
{
    const int idx = blockIdx.x * 256 + threadIdx.x;   // TOK*DI
    const int token = idx >> 11;
    const int ch = idx & (DI - 1);
    const float xv = fmaf(ssm[token * NXP], W_dt[ch], b_dt[ch]);
    dtout[idx] = (xv > 15.f) ? xv : log1pf(expf(xv));
}

// ----------------------------- selective scan ------------------------------
// lane = state n within 16-lane half-warp; half-warp = one channel.
// Block: 256 thr = 8 warps = 16 channels. Grid: (DI/16, BATCH).
__global__ void __launch_bounds__(256) scan_kernel(
    const float* __restrict__ ssm, const float* __restrict__ dt,
    const float* __restrict__ xconv, const float* __restrict__ xz,
    const float* __restrict__ A_log, const float* __restrict__ Dp,
    float* __restrict__ yout)
{
    const int lane = threadIdx.x & 31;
    const int warp = threadIdx.x >> 5;
    const int n = lane & 15;
    const int half = lane >> 4;
    const int ch = blockIdx.x * 16 + warp * 2 + half;
    const int b = blockIdx.y;

    const float An = -expf(A_log[ch * DS + n]);
    const float Dch = Dp[ch];

    const float* ssm_b = ssm + (size_t)b * SEQL * NXP;
    const float* dt_b = dt + (size_t)b * SEQL * DI + ch;
    const float* xc_b = xconv + (size_t)b * SEQL * DI + ch;
    const float* z_b = xz + (size_t)b * SEQL * (2 * DI) + DI + ch;
    float* y_b = yout + (size_t)b * SEQL * DI + ch;

    float h = 0.f;
    for (int t = 0; t < SEQL; ++t) {
        const float* row = ssm_b + t * NXP;
        const float Bv = row[1 + n];
        const float Cv = row[1 + DS + n];
        const float dtv = dt_b[(size_t)t * DI];
        const float xcv = xc_b[(size_t)t * DI];
        const float ab = __expf(dtv * An);
        h = fmaf(ab, h, dtv * xcv * Bv);
        float p = h * Cv;
        p += __shfl_xor_sync(0xffffffffu, p, 1);
        p += __shfl_xor_sync(0xffffffffu, p, 2);
        p += __shfl_xor_sync(0xffffffffu, p, 4);
        p += __shfl_xor_sync(0xffffffffu, p, 8);
        if (n == 0) {
            const float z = z_b[(size_t)t * (2 * DI)];
            const float sz = z / (1.f + __expf(-z));
            y_b[(size_t)t * DI] = (p + xcv * Dch) * sz;
        }
    }
}

// ---------------------------------------------------------------------------
extern "C" void kernel_launch(void* const* d_in, const int* in_sizes, int n_in,
                              void* d_out, int out_size)
{
    const float* x      = (const float*)d_in[0];
    const float* W_in   = (const float*)d_in[1];
    const float* conv_w = (const float*)d_in[2];
    const float* conv_b = (const float*)d_in[3];
    const float* W_xproj= (const float*)d_in[4];
    const float* W_dt   = (const float*)d_in[5];
    const float* b_dt   = (const float*)d_in[6];
    const float* A_log  = (const float*)d_in[7];
    const float* Dp     = (const float*)d_in[8];
    const float* W_out  = (const float*)d_in[9];
    const float* norm_w = (const float*)d_in[10];
    float* out = (float*)d_out;

    float *p_xn, *p_xz, *p_xconv, *p_ssm, *p_WxT, *p_dt, *p_y;
    cudaGetSymbolAddress((void**)&p_xn, g_xn);
    cudaGetSymbolAddress((void**)&p_xz, g_xz);
    cudaGetSymbolAddress((void**)&p_xconv, g_xconv);
    cudaGetSymbolAddress((void**)&p_ssm, g_ssm);
    cudaGetSymbolAddress((void**)&p_WxT, g_WxT);
    cudaGetSymbolAddress((void**)&p_dt, g_dt);
    cudaGetSymbolAddress((void**)&p_y, g_y);

    // 1) rmsnorm
    rmsnorm_kernel<<<TOK, 256>>>(x, norm_w, p_xn);

    // 2) xz = xn @ W_in   [2048,1024]@[1024,4096]
    sgemm_kernel<false><<<dim3(2 * DI / 128, TOK / 128), 256>>>(
        p_xn, W_in, nullptr, p_xz, TOK, 2 * DI, DM);

    // 3) conv + silu
    conv_silu_kernel<<<TOK * DI / 256, 256>>>(p_xz, conv_w, conv_b, p_xconv);

    // 4) xproj
    wxt_kernel<<<(DI * NXP + 255) / 256, 256>>>(W_xproj, p_WxT);
    xproj_kernel<<<TOK / 8, 256>>>(p_xconv, p_WxT, p_ssm);

    // 5) dt
    dt_kernel<<<TOK * DI / 256, 256>>>(p_ssm, W_dt, b_dt, p_dt);

    // 6) scan + gate
    scan_kernel<<<dim3(DI / 16, 2), 256>>>(p_ssm, p_dt, p_xconv, p_xz,
                                           A_log, Dp, p_y);

    // 7) out = x + y @ W_out   [2048,2048]@[2048,1024]
    sgemm_kernel<true><<<dim3(DM / 128, TOK / 128), 256>>>(
        p_y, W_out, x, out, TOK, DM, DI);
}

// round 5
// speedup vs baseline: 1.3359x; 1.3359x over previous
#include <cuda_runtime.h>
#include <cuda_bf16.h>
#include <math.h>
#include <stdint.h>

// ---------------------------------------------------------------------------
// MambaBlock: B=2, S=1024, D_MODEL=1024, D_INNER=2048, D_STATE=16, D_CONV=4
// Round 3: tcgen05 unavailable (harness targets compute_103 non-'a').
// Both large GEMMs via mma.sync.m16n8k8 tf32 (HMMA tensor path, sm_80+ class),
// cp.async double-buffered 128x128x32 tiles.
// ---------------------------------------------------------------------------

#define TOK 2048
#define DM  1024
#define DI  2048
#define DS  16
#define NXP 33
#define SEQL 1024

__device__ float g_xn[TOK * DM];
__device__ float g_xz[TOK * 2 * DI];
__device__ float g_xconv[TOK * DI];
__device__ float g_ssm[TOK * NXP];
__device__ float g_WxT[NXP * DI];
__device__ float g_dt[TOK * DI];
__device__ float g_y[TOK * DI];
__device__ float g_WinT[2 * DI * DM];   // [4096,1024]
__device__ float g_WoutT[DM * DI];      // [1024,2048]

// ------------------------------ helpers ------------------------------------
__device__ __forceinline__ uint32_t smem_u32(const void* p) {
    uint32_t a;
    asm("{ .reg .u64 t; cvta.to.shared.u64 t, %1; cvt.u32.u64 %0, t; }" : "=r"(a) : "l"(p));
    return a;
}
__device__ __forceinline__ uint32_t f2tf32(float f) {
    uint32_t r;
    asm("cvt.rna.tf32.f32 %0, %1;" : "=r"(r) : "f"(f));
    return r;
}
__device__ __forceinline__ void cp_async16(uint32_t dst, const void* src) {
    asm volatile("cp.async.cg.shared.global [%0], [%1], 16;" :: "r"(dst), "l"(src));
}
__device__ __forceinline__ void cp_commit() {
    asm volatile("cp.async.commit_group;");
}
__device__ __forceinline__ void cp_wait0() {
    asm volatile("cp.async.wait_group 0;" ::: "memory");
}
__device__ __forceinline__ void mma_tf32(float* d, const uint32_t* a, const uint32_t* b) {
    asm volatile(
        "mma.sync.aligned.m16n8k8.row.col.f32.tf32.tf32.f32 "
        "{%0,%1,%2,%3}, {%4,%5,%6,%7}, {%8,%9}, {%0,%1,%2,%3};"
        : "+f"(d[0]), "+f"(d[1]), "+f"(d[2]), "+f"(d[3])
        : "r"(a[0]), "r"(a[1]), "r"(a[2]), "r"(a[3]), "r"(b[0]), "r"(b[1]));
}

// ------------------------- mma.sync tf32 GEMM ------------------------------
// C[M,N] = A[M,K] @ Bt[N,K]^T (+ Rsd).  Grid: (N/128, M/128). Block 256.
// SMEM float layout: A0[128*36] A1[128*36] B0[128*36] B1[128*36]
#define SA 36
#define ABUF (128 * SA)
#define GSMEM (4 * ABUF * 4)

template <bool RES>
__global__ void __launch_bounds__(256, 1) gemm_mma_kernel(
    const float* __restrict__ A, const float* __restrict__ Bt,
    const float* __restrict__ Rsd, float* __restrict__ C,
    int Nout, int K)
{
    extern __shared__ __align__(16) float smem[];
    float* As = smem;                 // 2 bufs
    float* Bs = smem + 2 * ABUF;      // 2 bufs
    const uint32_t as_u = smem_u32(As);
    const uint32_t bs_u = smem_u32(Bs);

    const int tid = threadIdx.x;
    const int wid = tid >> 5;
    const int lane = tid & 31;
    const int wr = wid & 3;           // 4 warp-rows of 32
    const int wc = wid >> 2;          // 2 warp-cols of 64
    const int g = lane >> 2;          // group id 0..7
    const int tig = lane & 3;         // thread in group

    const int row0 = blockIdx.y * 128;
    const int col0 = blockIdx.x * 128;
    const int KT = K >> 5;            // K / 32

    // per-thread load slots: 4 passes, 8 threads/row, 16B each
    const int lr = tid >> 3;          // base row (of 32 per pass)
    const int lc = (tid & 7) << 2;    // float col within 32

    float acc[2][8][4];
    #pragma unroll
    for (int i = 0; i < 2; i++)
        #pragma unroll
        for (int j = 0; j < 8; j++)
            #pragma unroll
            for (int q = 0; q < 4; q++) acc[i][j][q] = 0.f;

    // prologue: load ktile 0 into buf 0
    {
        #pragma unroll
        for (int p = 0; p < 4; ++p) {
            const int r = p * 32 + lr;
            cp_async16(as_u + (r * SA + lc) * 4, &A[(size_t)(row0 + r) * K + lc]);
            cp_async16(bs_u + (r * SA + lc) * 4, &Bt[(size_t)(col0 + r) * K + lc]);
        }
        cp_commit();
    }

    for (int i = 0; i < KT; ++i) {
        cp_wait0();
        __syncthreads();
        const int b = i & 1;
        // prefetch next ktile into other buffer
        if (i + 1 < KT) {
            const int nb = (i + 1) & 1;
            const int k0 = (i + 1) << 5;
            #pragma unroll
            for (int p = 0; p < 4; ++p) {
                const int r = p * 32 + lr;
                cp_async16(as_u + (nb * ABUF + r * SA + lc) * 4,
                           &A[(size_t)(row0 + r) * K + k0 + lc]);
                cp_async16(bs_u + (nb * ABUF + r * SA + lc) * 4,
                           &Bt[(size_t)(col0 + r) * K + k0 + lc]);
            }
            cp_commit();
        }
        // compute on buffer b
        const float* Ab = As + b * ABUF;
        const float* Bb = Bs + b * ABUF;
        #pragma unroll
        for (int kk = 0; kk < 4; ++kk) {
            const int k = kk << 3;
            uint32_t afr[2][4];
            #pragma unroll
            for (int mt = 0; mt < 2; ++mt) {
                const int rb = wr * 32 + mt * 16;
                afr[mt][0] = f2tf32(Ab[(rb + g) * SA + k + tig]);
                afr[mt][1] = f2tf32(Ab[(rb + g + 8) * SA + k + tig]);
                afr[mt][2] = f2tf32(Ab[(rb + g) * SA + k + tig + 4]);
                afr[mt][3] = f2tf32(Ab[(rb + g + 8) * SA + k + tig + 4]);
            }
            uint32_t bfr[8][2];
            #pragma unroll
            for (int nt = 0; nt < 8; ++nt) {
                const int cb = wc * 64 + nt * 8;
                bfr[nt][0] = f2tf32(Bb[(cb + g) * SA + k + tig]);
                bfr[nt][1] = f2tf32(Bb[(cb + g) * SA + k + tig + 4]);
            }
            #pragma unroll
            for (int mt = 0; mt < 2; ++mt)
                #pragma unroll
                for (int nt = 0; nt < 8; ++nt)
                    mma_tf32(acc[mt][nt], afr[mt], bfr[nt]);
        }
        __syncthreads();
    }

    // epilogue
    #pragma unroll
    for (int mt = 0; mt < 2; ++mt) {
        const int r0 = row0 + wr * 32 + mt * 16 + g;
        #pragma unroll
        for (int nt = 0; nt < 8; ++nt) {
            const int c = col0 + wc * 64 + nt * 8 + tig * 2;
            float2 v0 = make_float2(acc[mt][nt][0], acc[mt][nt][1]);
            float2 v1 = make_float2(acc[mt][nt][2], acc[mt][nt][3]);
            if (RES) {
                float2 r0v = *reinterpret_cast<const float2*>(&Rsd[(size_t)r0 * Nout + c]);
                float2 r1v = *reinterpret_cast<const float2*>(&Rsd[(size_t)(r0 + 8) * Nout + c]);
                v0.x += r0v.x; v0.y += r0v.y;
                v1.x += r1v.x; v1.y += r1v.y;
            }
            *reinterpret_cast<float2*>(&C[(size_t)r0 * Nout + c]) = v0;
            *reinterpret_cast<float2*>(&C[(size_t)(r0 + 8) * Nout + c]) = v1;
        }
    }
}

// ------------------------------ transpose ----------------------------------
__global__ void __launch_bounds__(256) transpose_kernel(
    const float* __restrict__ in, float* __restrict__ out, int R, int Ccols)
{
    __shared__ float tile[32][33];
    const int c0 = blockIdx.x * 32, r0 = blockIdx.y * 32;
    const int x = threadIdx.x, y = threadIdx.y;
    #pragma unroll
    for (int j = 0; j < 32; j += 8)
        tile[y + j][x] = in[(size_t)(r0 + y + j) * Ccols + c0 + x];
    __syncthreads();
    #pragma unroll
    for (int j = 0; j < 32; j += 8)
        out[(size_t)(c0 + y + j) * R + r0 + x] = tile[x][y + j];
}

// ------------------------------ rmsnorm ------------------------------------
__global__ void __launch_bounds__(256) rmsnorm_kernel(
    const float* __restrict__ x, const float* __restrict__ w, float* __restrict__ xn)
{
    const int token = blockIdx.x;
    const int tid = threadIdx.x;
    const float4* x4 = reinterpret_cast<const float4*>(x + (size_t)token * DM);
    float4 v = x4[tid];
    float s = v.x * v.x + v.y * v.y + v.z * v.z + v.w * v.w;
    __shared__ float red[8];
    #pragma unroll
    for (int o = 16; o; o >>= 1) s += __shfl_xor_sync(0xffffffffu, s, o);
    if ((tid & 31) == 0) red[tid >> 5] = s;
    __syncthreads();
    if (tid < 32) {
        float t = (tid < 8) ? red[tid] : 0.f;
        #pragma unroll
        for (int o = 4; o; o >>= 1) t += __shfl_xor_sync(0xffffffffu, t, o);
        if (tid == 0) red[0] = t;
    }
    __syncthreads();
    const float ms = red[0] * (1.f / (float)DM);
    const float r = rsqrtf(ms + 1.1920928955078125e-07f);
    const float4* w4 = reinterpret_cast<const float4*>(w);
    float4 wv = w4[tid];
    float4 o;
    o.x = v.x * r * wv.x; o.y = v.y * r * wv.y;
    o.z = v.z * r * wv.z; o.w = v.w * r * wv.w;
    reinterpret_cast<float4*>(xn + (size_t)token * DM)[tid] = o;
}

// ---------------------- causal depthwise conv + silu -----------------------
__global__ void __launch_bounds__(256) conv_silu_kernel(
    const float* __restrict__ xz, const float* __restrict__ cw,
    const float* __restrict__ cb, float* __restrict__ xconv)
{
    const int idx = blockIdx.x * 256 + threadIdx.x;
    const int ch = idx & (DI - 1);
    const int token = idx >> 11;
    const int t = token & (SEQL - 1);
    const int b = token >> 10;
    float acc = cb[ch];
    const float* base = xz + (size_t)(b * SEQL) * (2 * DI) + ch;
    #pragma unroll
    for (int k = 0; k < 4; ++k) {
        const int tt = t - 3 + k;
        if (tt >= 0)
            acc = fmaf(base[(size_t)tt * (2 * DI)], cw[ch * 4 + k], acc);
    }
    xconv[idx] = acc / (1.f + __expf(-acc));
}

// ------------------------ W_xproj transpose --------------------------------
__global__ void wxt_kernel(const float* __restrict__ W, float* __restrict__ WT)
{
    const int idx = blockIdx.x * 256 + threadIdx.x;
    if (idx < DI * NXP) {
        const int k = idx / NXP;
        const int c = idx - k * NXP;
        WT[c * DI + k] = W[idx];
    }
}

// ----------------------------- xproj ---------------------------------------
__global__ void __launch_bounds__(256) xproj_kernel(
    const float* __restrict__ xconv, const float* __restrict__ WxT,
    float* __restrict__ ssm)
{
    const int warp = threadIdx.x >> 5;
    const int lane = threadIdx.x & 31;
    const int token = blockIdx.x * 8 + warp;
    const float4* x4 = reinterpret_cast<const float4*>(xconv + (size_t)token * DI);
    for (int c = 0; c < NXP; ++c) {
        const float4* w4 = reinterpret_cast<const float4*>(WxT + (size_t)c * DI);
        float acc = 0.f;
        for (int i = lane; i < DI / 4; i += 32) {
            float4 a = x4[i];
            float4 w = w4[i];
            acc = fmaf(a.x, w.x, acc);
            acc = fmaf(a.y, w.y, acc);
            acc = fmaf(a.z, w.z, acc);
            acc = fmaf(a.w, w.w, acc);
        }
        #pragma unroll
        for (int o = 16; o; o >>= 1) acc += __shfl_xor_sync(0xffffffffu, acc, o);
        if (lane == 0) ssm[token * NXP + c] = acc;
    }
}

// ----------------------------- dt = softplus --------------------------------
__global__ void __launch_bounds__(256) dt_kernel(
    const float* __restrict__ ssm, const float* __restrict__ W_dt,
    const float* __restrict__ b_dt, float* __restrict__ dtout)
{
    const int idx = blockIdx.x * 256 + threadIdx.x;
    const int token = idx >> 11;
    const int ch = idx & (DI - 1);
    const float xv = fmaf(ssm[token * NXP], W_dt[ch], b_dt[ch]);
    dtout[idx] = (xv > 15.f) ? xv : log1pf(expf(xv));
}

// ----------------------------- selective scan ------------------------------
__global__ void __launch_bounds__(256) scan_kernel(
    const float* __restrict__ ssm, const float* __restrict__ dt,
    const float* __restrict__ xconv, const float* __restrict__ xz,
    const float* __restrict__ A_log, const float* __restrict__ Dp,
    float* __restrict__ yout)
{
    const int lane = threadIdx.x & 31;
    const int warp = threadIdx.x >> 5;
    const int n = lane & 15;
    const int half = lane >> 4;
    const int ch = blockIdx.x * 16 + warp * 2 + half;
    const int b = blockIdx.y;

    const float An = -expf(A_log[ch * DS + n]);
    const float Dch = Dp[ch];

    const float* ssm_b = ssm + (size_t)b * SEQL * NXP;
    const float* dt_b = dt + (size_t)b * SEQL * DI + ch;
    const float* xc_b = xconv + (size_t)b * SEQL * DI + ch;
    const float* z_b = xz + (size_t)b * SEQL * (2 * DI) + DI + ch;
    float* y_b = yout + (size_t)b * SEQL * DI + ch;

    float h = 0.f;
    for (int t = 0; t < SEQL; ++t) {
        const float* row = ssm_b + t * NXP;
        const float Bv = row[1 + n];
        const float Cv = row[1 + DS + n];
        const float dtv = dt_b[(size_t)t * DI];
        const float xcv = xc_b[(size_t)t * DI];
        const float ab = __expf(dtv * An);
        h = fmaf(ab, h, dtv * xcv * Bv);
        float p = h * Cv;
        p += __shfl_xor_sync(0xffffffffu, p, 1);
        p += __shfl_xor_sync(0xffffffffu, p, 2);
        p += __shfl_xor_sync(0xffffffffu, p, 4);
        p += __shfl_xor_sync(0xffffffffu, p, 8);
        if (n == 0) {
            const float z = z_b[(size_t)t * (2 * DI)];
            const float sz = z / (1.f + __expf(-z));
            y_b[(size_t)t * DI] = (p + xcv * Dch) * sz;
        }
    }
}

// ---------------------------------------------------------------------------
extern "C" void kernel_launch(void* const* d_in, const int* in_sizes, int n_in,
                              void* d_out, int out_size)
{
    const float* x      = (const float*)d_in[0];
    const float* W_in   = (const float*)d_in[1];
    const float* conv_w = (const float*)d_in[2];
    const float* conv_b = (const float*)d_in[3];
    const float* W_xproj= (const float*)d_in[4];
    const float* W_dt   = (const float*)d_in[5];
    const float* b_dt   = (const float*)d_in[6];
    const float* A_log  = (const float*)d_in[7];
    const float* Dp     = (const float*)d_in[8];
    const float* W_out  = (const float*)d_in[9];
    const float* norm_w = (const float*)d_in[10];
    float* out = (float*)d_out;

    float *p_xn, *p_xz, *p_xconv, *p_ssm, *p_WxT, *p_dt, *p_y, *p_WinT, *p_WoutT;
    cudaGetSymbolAddress((void**)&p_xn, g_xn);
    cudaGetSymbolAddress((void**)&p_xz, g_xz);
    cudaGetSymbolAddress((void**)&p_xconv, g_xconv);
    cudaGetSymbolAddress((void**)&p_ssm, g_ssm);
    cudaGetSymbolAddress((void**)&p_WxT, g_WxT);
    cudaGetSymbolAddress((void**)&p_dt, g_dt);
    cudaGetSymbolAddress((void**)&p_y, g_y);
    cudaGetSymbolAddress((void**)&p_WinT, g_WinT);
    cudaGetSymbolAddress((void**)&p_WoutT, g_WoutT);

    static bool attr_done = false;
    if (!attr_done) {
        cudaFuncSetAttribute(gemm_mma_kernel<false>,
                             cudaFuncAttributeMaxDynamicSharedMemorySize, GSMEM);
        cudaFuncSetAttribute(gemm_mma_kernel<true>,
                             cudaFuncAttributeMaxDynamicSharedMemorySize, GSMEM);
        attr_done = true;
    }

    // weight transposes (B operands must be [N,K])
    transpose_kernel<<<dim3((2 * DI) / 32, DM / 32), dim3(32, 8)>>>(W_in, p_WinT, DM, 2 * DI);
    transpose_kernel<<<dim3(DM / 32, DI / 32), dim3(32, 8)>>>(W_out, p_WoutT, DI, DM);

    // 1) rmsnorm
    rmsnorm_kernel<<<TOK, 256>>>(x, norm_w, p_xn);

    // 2) xz = xn @ W_in   [2048,1024]@[1024,4096]
    gemm_mma_kernel<false><<<dim3((2 * DI) / 128, TOK / 128), 256, GSMEM>>>(
        p_xn, p_WinT, nullptr, p_xz, 2 * DI, DM);

    // 3) conv + silu
    conv_silu_kernel<<<TOK * DI / 256, 256>>>(p_xz, conv_w, conv_b, p_xconv);

    // 4) xproj
    wxt_kernel<<<(DI * NXP + 255) / 256, 256>>>(W_xproj, p_WxT);
    xproj_kernel<<<TOK / 8, 256>>>(p_xconv, p_WxT, p_ssm);

    // 5) dt
    dt_kernel<<<TOK * DI / 256, 256>>>(p_ssm, W_dt, b_dt, p_dt);

    // 6) scan + gate
    scan_kernel<<<dim3(DI / 16, 2), 256>>>(p_ssm, p_dt, p_xconv, p_xz,
                                           A_log, Dp, p_y);

    // 7) out = x + y @ W_out   [2048,2048]@[2048,1024]
    gemm_mma_kernel<true><<<dim3(DM / 128, TOK / 128), 256, GSMEM>>>(
        p_y, p_WoutT, x, out, DM, DI);
}

// round 6
// speedup vs baseline: 2.7887x; 2.0875x over previous
#include <cuda_runtime.h>
#include <cuda_bf16.h>
#include <math.h>
#include <stdint.h>

// ---------------------------------------------------------------------------
// MambaBlock: B=2, S=1024, D_MODEL=1024, D_INNER=2048, D_STATE=16, D_CONV=4
// Round 6: chunked parallel scan (16 chunks), transposed [ch][t] time-series
// layout, smem-tiled xproj with k-split, GEMMs at 2 CTAs/SM.
// ---------------------------------------------------------------------------

#define TOK 2048
#define DM  1024
#define DI  2048
#define DS  16
#define NXP 33
#define SEQL 1024
#define NCHUNK 16
#define CLEN 64   // SEQL / NCHUNK

__device__ float g_xn[TOK * DM];
__device__ float g_xz[TOK * 2 * DI];
__device__ float g_xconv_t[TOK * DI];      // [b][ch][t]
__device__ float g_ssm[TOK * NXP];
__device__ float g_y[TOK * DI];
__device__ float g_yt[TOK * DI];           // [b][ch][t]  (pre-gate ssm out)
__device__ float g_WinT[2 * DI * DM];
__device__ float g_WoutT[DM * DI];
__device__ float g_xp[8 * NXP * TOK];      // xproj partials [ks][c][tok]
__device__ float g_P[2 * NCHUNK * DI * DS];
__device__ float g_hL[2 * NCHUNK * DI * DS];
__device__ float g_h0[2 * NCHUNK * DI * DS];

// ------------------------------ helpers ------------------------------------
__device__ __forceinline__ uint32_t smem_u32(const void* p) {
    uint32_t a;
    asm("{ .reg .u64 t; cvta.to.shared.u64 t, %1; cvt.u32.u64 %0, t; }" : "=r"(a) : "l"(p));
    return a;
}
__device__ __forceinline__ uint32_t f2tf32(float f) {
    uint32_t r;
    asm("cvt.rna.tf32.f32 %0, %1;" : "=r"(r) : "f"(f));
    return r;
}
__device__ __forceinline__ void cp_async16(uint32_t dst, const void* src) {
    asm volatile("cp.async.cg.shared.global [%0], [%1], 16;" :: "r"(dst), "l"(src));
}
__device__ __forceinline__ void cp_commit() {
    asm volatile("cp.async.commit_group;");
}
__device__ __forceinline__ void cp_wait0() {
    asm volatile("cp.async.wait_group 0;" ::: "memory");
}
__device__ __forceinline__ void mma_tf32(float* d, const uint32_t* a, const uint32_t* b) {
    asm volatile(
        "mma.sync.aligned.m16n8k8.row.col.f32.tf32.tf32.f32 "
        "{%0,%1,%2,%3}, {%4,%5,%6,%7}, {%8,%9}, {%0,%1,%2,%3};"
        : "+f"(d[0]), "+f"(d[1]), "+f"(d[2]), "+f"(d[3])
        : "r"(a[0]), "r"(a[1]), "r"(a[2]), "r"(a[3]), "r"(b[0]), "r"(b[1]));
}
__device__ __forceinline__ float softplus_f(float x) {
    return (x > 15.f) ? x : log1pf(expf(x));
}
__device__ __forceinline__ float silu_f(float x) {
    return x / (1.f + __expf(-x));
}

// ------------------------- mma.sync tf32 GEMM ------------------------------
#define SA 36
#define ABUF (128 * SA)
#define GSMEM (4 * ABUF * 4)

template <bool RES>
__global__ void __launch_bounds__(256, 2) gemm_mma_kernel(
    const float* __restrict__ A, const float* __restrict__ Bt,
    const float* __restrict__ Rsd, float* __restrict__ C,
    int Nout, int K)
{
    extern __shared__ __align__(16) float smem[];
    float* As = smem;
    float* Bs = smem + 2 * ABUF;
    const uint32_t as_u = smem_u32(As);
    const uint32_t bs_u = smem_u32(Bs);

    const int tid = threadIdx.x;
    const int wid = tid >> 5;
    const int lane = tid & 31;
    const int wr = wid & 3;
    const int wc = wid >> 2;
    const int g = lane >> 2;
    const int tig = lane & 3;

    const int row0 = blockIdx.y * 128;
    const int col0 = blockIdx.x * 128;
    const int KT = K >> 5;

    const int lr = tid >> 3;
    const int lc = (tid & 7) << 2;

    float acc[2][8][4];
    #pragma unroll
    for (int i = 0; i < 2; i++)
        #pragma unroll
        for (int j = 0; j < 8; j++)
            #pragma unroll
            for (int q = 0; q < 4; q++) acc[i][j][q] = 0.f;

    {
        #pragma unroll
        for (int p = 0; p < 4; ++p) {
            const int r = p * 32 + lr;
            cp_async16(as_u + (r * SA + lc) * 4, &A[(size_t)(row0 + r) * K + lc]);
            cp_async16(bs_u + (r * SA + lc) * 4, &Bt[(size_t)(col0 + r) * K + lc]);
        }
        cp_commit();
    }

    for (int i = 0; i < KT; ++i) {
        cp_wait0();
        __syncthreads();
        const int b = i & 1;
        if (i + 1 < KT) {
            const int nb = (i + 1) & 1;
            const int k0 = (i + 1) << 5;
            #pragma unroll
            for (int p = 0; p < 4; ++p) {
                const int r = p * 32 + lr;
                cp_async16(as_u + (nb * ABUF + r * SA + lc) * 4,
                           &A[(size_t)(row0 + r) * K + k0 + lc]);
                cp_async16(bs_u + (nb * ABUF + r * SA + lc) * 4,
                           &Bt[(size_t)(col0 + r) * K + k0 + lc]);
            }
            cp_commit();
        }
        const float* Ab = As + b * ABUF;
        const float* Bb = Bs + b * ABUF;
        #pragma unroll
        for (int kk = 0; kk < 4; ++kk) {
            const int k = kk << 3;
            uint32_t afr[2][4];
            #pragma unroll
            for (int mt = 0; mt < 2; ++mt) {
                const int rb = wr * 32 + mt * 16;
                afr[mt][0] = f2tf32(Ab[(rb + g) * SA + k + tig]);
                afr[mt][1] = f2tf32(Ab[(rb + g + 8) * SA + k + tig]);
                afr[mt][2] = f2tf32(Ab[(rb + g) * SA + k + tig + 4]);
                afr[mt][3] = f2tf32(Ab[(rb + g + 8) * SA + k + tig + 4]);
            }
            uint32_t bfr[8][2];
            #pragma unroll
            for (int nt = 0; nt < 8; ++nt) {
                const int cb = wc * 64 + nt * 8;
                bfr[nt][0] = f2tf32(Bb[(cb + g) * SA + k + tig]);
                bfr[nt][1] = f2tf32(Bb[(cb + g) * SA + k + tig + 4]);
            }
            #pragma unroll
            for (int mt = 0; mt < 2; ++mt)
                #pragma unroll
                for (int nt = 0; nt < 8; ++nt)
                    mma_tf32(acc[mt][nt], afr[mt], bfr[nt]);
        }
        __syncthreads();
    }

    #pragma unroll
    for (int mt = 0; mt < 2; ++mt) {
        const int r0 = row0 + wr * 32 + mt * 16 + g;
        #pragma unroll
        for (int nt = 0; nt < 8; ++nt) {
            const int c = col0 + wc * 64 + nt * 8 + tig * 2;
            float2 v0 = make_float2(acc[mt][nt][0], acc[mt][nt][1]);
            float2 v1 = make_float2(acc[mt][nt][2], acc[mt][nt][3]);
            if (RES) {
                float2 r0v = *reinterpret_cast<const float2*>(&Rsd[(size_t)r0 * Nout + c]);
                float2 r1v = *reinterpret_cast<const float2*>(&Rsd[(size_t)(r0 + 8) * Nout + c]);
                v0.x += r0v.x; v0.y += r0v.y;
                v1.x += r1v.x; v1.y += r1v.y;
            }
            *reinterpret_cast<float2*>(&C[(size_t)r0 * Nout + c]) = v0;
            *reinterpret_cast<float2*>(&C[(size_t)(r0 + 8) * Nout + c]) = v1;
        }
    }
}

// ------------------------------ transpose ----------------------------------
__global__ void __launch_bounds__(256) transpose_kernel(
    const float* __restrict__ in, float* __restrict__ out, int R, int Ccols)
{
    __shared__ float tile[32][33];
    const int c0 = blockIdx.x * 32, r0 = blockIdx.y * 32;
    const int x = threadIdx.x, y = threadIdx.y;
    #pragma unroll
    for (int j = 0; j < 32; j += 8)
        tile[y + j][x] = in[(size_t)(r0 + y + j) * Ccols + c0 + x];
    __syncthreads();
    #pragma unroll
    for (int j = 0; j < 32; j += 8)
        out[(size_t)(c0 + y + j) * R + r0 + x] = tile[x][y + j];
}

// ------------------------------ rmsnorm ------------------------------------
__global__ void __launch_bounds__(256) rmsnorm_kernel(
    const float* __restrict__ x, const float* __restrict__ w, float* __restrict__ xn)
{
    const int token = blockIdx.x;
    const int tid = threadIdx.x;
    const float4* x4 = reinterpret_cast<const float4*>(x + (size_t)token * DM);
    float4 v = x4[tid];
    float s = v.x * v.x + v.y * v.y + v.z * v.z + v.w * v.w;
    __shared__ float red[8];
    #pragma unroll
    for (int o = 16; o; o >>= 1) s += __shfl_xor_sync(0xffffffffu, s, o);
    if ((tid & 31) == 0) red[tid >> 5] = s;
    __syncthreads();
    if (tid < 32) {
        float t = (tid < 8) ? red[tid] : 0.f;
        #pragma unroll
        for (int o = 4; o; o >>= 1) t += __shfl_xor_sync(0xffffffffu, t, o);
        if (tid == 0) red[0] = t;
    }
    __syncthreads();
    const float ms = red[0] * (1.f / (float)DM);
    const float r = rsqrtf(ms + 1.1920928955078125e-07f);
    const float4* w4 = reinterpret_cast<const float4*>(w);
    float4 wv = w4[tid];
    float4 o;
    o.x = v.x * r * wv.x; o.y = v.y * r * wv.y;
    o.z = v.z * r * wv.z; o.w = v.w * r * wv.w;
    reinterpret_cast<float4*>(xn + (size_t)token * DM)[tid] = o;
}

// ------------- causal depthwise conv + silu, transposed output -------------
// out xconv_t[b][ch][t].  block(32,8): tile 32 ch x 32 t.  grid(DI/32, S/32, B)
__global__ void __launch_bounds__(256) conv_silu_t_kernel(
    const float* __restrict__ xz, const float* __restrict__ cw,
    const float* __restrict__ cb, float* __restrict__ xconv_t)
{
    __shared__ float tile[35][33];    // rows = t0-3 .. t0+31
    const int ch0 = blockIdx.x * 32;
    const int t0 = blockIdx.y * 32;
    const int b = blockIdx.z;
    const int tx = threadIdx.x, ty = threadIdx.y;

    for (int j = ty; j < 35; j += 8) {
        const int tg = t0 + j - 3;
        tile[j][tx] = (tg >= 0) ? xz[(size_t)(b * SEQL + tg) * (2 * DI) + ch0 + tx] : 0.f;
    }
    __syncthreads();

    #pragma unroll
    for (int q = 0; q < 4; ++q) {
        const int chl = ty + q * 8;
        const int ch = ch0 + chl;
        float acc = cb[ch];
        #pragma unroll
        for (int k = 0; k < 4; ++k)
            acc = fmaf(tile[tx + k][chl], cw[ch * 4 + k], acc);
        xconv_t[((size_t)b * DI + ch) * SEQL + t0 + tx] = silu_f(acc);
    }
}

// ---------------------- xproj partials (k-split) ---------------------------
// part[ks][c][tok] = sum over k in split ks of xconv_t[k][tok] * W[k][c]
__global__ void __launch_bounds__(128) xproj_part_kernel(
    const float* __restrict__ xconv_t, const float* __restrict__ W,
    float* __restrict__ part)
{
    __shared__ float Wbuf[64][NXP];
    const int tok = blockIdx.x * 128 + threadIdx.x;
    const int b = tok >> 10;
    const int t = tok & (SEQL - 1);
    const int ks = blockIdx.y;
    const int kbase = ks * (DI / 8);

    float acc[NXP];
    #pragma unroll
    for (int c = 0; c < NXP; ++c) acc[c] = 0.f;

    for (int kc = 0; kc < DI / 8; kc += 64) {
        __syncthreads();
        for (int i = threadIdx.x; i < 64 * NXP; i += 128) {
            const int kr = i / NXP, c = i - kr * NXP;
            Wbuf[kr][c] = W[(size_t)(kbase + kc + kr) * NXP + c];
        }
        __syncthreads();
        #pragma unroll 4
        for (int kr = 0; kr < 64; ++kr) {
            const float xv = xconv_t[((size_t)b * DI + kbase + kc + kr) * SEQL + t];
            #pragma unroll
            for (int c = 0; c < NXP; ++c)
                acc[c] = fmaf(xv, Wbuf[kr][c], acc[c]);
        }
    }
    #pragma unroll
    for (int c = 0; c < NXP; ++c)
        part[((size_t)ks * NXP + c) * TOK + tok] = acc[c];
}

__global__ void __launch_bounds__(256) xproj_reduce_kernel(
    const float* __restrict__ part, float* __restrict__ ssm)
{
    const int idx = blockIdx.x * 256 + threadIdx.x;   // c*TOK + tok
    if (idx >= NXP * TOK) return;
    const int c = idx / TOK;
    const int tok = idx - c * TOK;
    float s = 0.f;
    #pragma unroll
    for (int ks = 0; ks < 8; ++ks)
        s += part[((size_t)ks * NXP + c) * TOK + tok];
    ssm[(size_t)tok * NXP + c] = s;
}

// --------------------------- scan phase A ----------------------------------
// per chunk: P = prod(ab), hL = local state.  half-warp = channel, lane = n.
__global__ void __launch_bounds__(256) scan_a_kernel(
    const float* __restrict__ ssm, const float* __restrict__ xconv_t,
    const float* __restrict__ A_log, const float* __restrict__ W_dt,
    const float* __restrict__ b_dt, float* __restrict__ Pout,
    float* __restrict__ hLout)
{
    const int lane = threadIdx.x & 31;
    const int warp = threadIdx.x >> 5;
    const int n = lane & 15;
    const int half = lane >> 4;
    const int ch = blockIdx.x * 16 + warp * 2 + half;
    const int chunk = blockIdx.y;
    const int b = blockIdx.z;

    const float An = -expf(A_log[ch * DS + n]);
    const float wdt = W_dt[ch];
    const float bdt = b_dt[ch];

    const float* srow = ssm + (size_t)(b * SEQL + chunk * CLEN) * NXP;
    const float* xc = xconv_t + ((size_t)b * DI + ch) * SEQL + chunk * CLEN;

    float h = 0.f, P = 1.f;
    #pragma unroll 4
    for (int t = 0; t < CLEN; ++t) {
        const float dtr = srow[0];
        const float Bv = srow[1 + n];
        const float xcv = xc[t];
        const float dtv = softplus_f(fmaf(dtr, wdt, bdt));
        const float ab = __expf(dtv * An);
        h = fmaf(ab, h, dtv * xcv * Bv);
        P *= ab;
        srow += NXP;
    }
    const size_t idx = (((size_t)b * NCHUNK + chunk) * DI + ch) * DS + n;
    Pout[idx] = P;
    hLout[idx] = h;
}

// --------------------------- scan phase B ----------------------------------
__global__ void __launch_bounds__(256) scan_b_kernel(
    const float* __restrict__ P, const float* __restrict__ hL,
    float* __restrict__ h0)
{
    const int gid = blockIdx.x * 256 + threadIdx.x;    // 2*DI*DS
    const int b = gid / (DI * DS);
    const int r = gid - b * (DI * DS);
    float h = 0.f;
    #pragma unroll
    for (int c = 0; c < NCHUNK; ++c) {
        const size_t idx = ((size_t)(b * NCHUNK + c)) * (DI * DS) + r;
        h0[idx] = h;
        h = fmaf(P[idx], h, hL[idx]);
    }
}

// --------------------------- scan phase C ----------------------------------
__global__ void __launch_bounds__(256) scan_c_kernel(
    const float* __restrict__ ssm, const float* __restrict__ xconv_t,
    const float* __restrict__ A_log, const float* __restrict__ W_dt,
    const float* __restrict__ b_dt, const float* __restrict__ Dp,
    const float* __restrict__ h0, float* __restrict__ yt)
{
    const int lane = threadIdx.x & 31;
    const int warp = threadIdx.x >> 5;
    const int n = lane & 15;
    const int half = lane >> 4;
    const int ch = blockIdx.x * 16 + warp * 2 + half;
    const int chunk = blockIdx.y;
    const int b = blockIdx.z;

    const float An = -expf(A_log[ch * DS + n]);
    const float wdt = W_dt[ch];
    const float bdt = b_dt[ch];
    const float Dch = Dp[ch];

    const float* srow = ssm + (size_t)(b * SEQL + chunk * CLEN) * NXP;
    const float* xc = xconv_t + ((size_t)b * DI + ch) * SEQL + chunk * CLEN;
    float* yrow = yt + ((size_t)b * DI + ch) * SEQL + chunk * CLEN;

    float h = h0[(((size_t)b * NCHUNK + chunk) * DI + ch) * DS + n];

    #pragma unroll 4
    for (int t = 0; t < CLEN; ++t) {
        const float dtr = srow[0];
        const float Bv = srow[1 + n];
        const float Cv = srow[1 + DS + n];
        const float xcv = xc[t];
        const float dtv = softplus_f(fmaf(dtr, wdt, bdt));
        const float ab = __expf(dtv * An);
        h = fmaf(ab, h, dtv * xcv * Bv);
        float p = h * Cv;
        p += __shfl_xor_sync(0xffffffffu, p, 1);
        p += __shfl_xor_sync(0xffffffffu, p, 2);
        p += __shfl_xor_sync(0xffffffffu, p, 4);
        p += __shfl_xor_sync(0xffffffffu, p, 8);
        if (n == 0) yrow[t] = fmaf(xcv, Dch, p);
        srow += NXP;
    }
}

// ------------------------- gate + transpose --------------------------------
// y[tok][ch] = yt[b][ch][t] * silu(z[tok][ch])
__global__ void __launch_bounds__(256) gate_kernel(
    const float* __restrict__ yt, const float* __restrict__ xz,
    float* __restrict__ y)
{
    __shared__ float tile[32][33];
    const int ch0 = blockIdx.x * 32;
    const int t0 = blockIdx.y * 32;
    const int b = blockIdx.z;
    const int tx = threadIdx.x, ty = threadIdx.y;
    #pragma unroll
    for (int j = 0; j < 32; j += 8)
        tile[ty + j][tx] = yt[((size_t)b * DI + ch0 + ty + j) * SEQL + t0 + tx];
    __syncthreads();
    #pragma unroll
    for (int j = 0; j < 32; j += 8) {
        const int tok = b * SEQL + t0 + ty + j;
        const float z = xz[(size_t)tok * (2 * DI) + DI + ch0 + tx];
        y[(size_t)tok * DI + ch0 + tx] = tile[tx][ty + j] * silu_f(z);
    }
}

// ---------------------------------------------------------------------------
extern "C" void kernel_launch(void* const* d_in, const int* in_sizes, int n_in,
                              void* d_out, int out_size)
{
    const float* x      = (const float*)d_in[0];
    const float* W_in   = (const float*)d_in[1];
    const float* conv_w = (const float*)d_in[2];
    const float* conv_b = (const float*)d_in[3];
    const float* W_xproj= (const float*)d_in[4];
    const float* W_dt   = (const float*)d_in[5];
    const float* b_dt   = (const float*)d_in[6];
    const float* A_log  = (const float*)d_in[7];
    const float* Dp     = (const float*)d_in[8];
    const float* W_out  = (const float*)d_in[9];
    const float* norm_w = (const float*)d_in[10];
    float* out = (float*)d_out;

    float *p_xn, *p_xz, *p_xct, *p_ssm, *p_y, *p_yt, *p_WinT, *p_WoutT;
    float *p_xp, *p_P, *p_hL, *p_h0;
    cudaGetSymbolAddress((void**)&p_xn, g_xn);
    cudaGetSymbolAddress((void**)&p_xz, g_xz);
    cudaGetSymbolAddress((void**)&p_xct, g_xconv_t);
    cudaGetSymbolAddress((void**)&p_ssm, g_ssm);
    cudaGetSymbolAddress((void**)&p_y, g_y);
    cudaGetSymbolAddress((void**)&p_yt, g_yt);
    cudaGetSymbolAddress((void**)&p_WinT, g_WinT);
    cudaGetSymbolAddress((void**)&p_WoutT, g_WoutT);
    cudaGetSymbolAddress((void**)&p_xp, g_xp);
    cudaGetSymbolAddress((void**)&p_P, g_P);
    cudaGetSymbolAddress((void**)&p_hL, g_hL);
    cudaGetSymbolAddress((void**)&p_h0, g_h0);

    static bool attr_done = false;
    if (!attr_done) {
        cudaFuncSetAttribute(gemm_mma_kernel<false>,
                             cudaFuncAttributeMaxDynamicSharedMemorySize, GSMEM);
        cudaFuncSetAttribute(gemm_mma_kernel<true>,
                             cudaFuncAttributeMaxDynamicSharedMemorySize, GSMEM);
        attr_done = true;
    }

    // weight transposes
    transpose_kernel<<<dim3((2 * DI) / 32, DM / 32), dim3(32, 8)>>>(W_in, p_WinT, DM, 2 * DI);
    transpose_kernel<<<dim3(DM / 32, DI / 32), dim3(32, 8)>>>(W_out, p_WoutT, DI, DM);

    // 1) rmsnorm
    rmsnorm_kernel<<<TOK, 256>>>(x, norm_w, p_xn);

    // 2) xz = xn @ W_in
    gemm_mma_kernel<false><<<dim3((2 * DI) / 128, TOK / 128), 256, GSMEM>>>(
        p_xn, p_WinT, nullptr, p_xz, 2 * DI, DM);

    // 3) conv + silu -> transposed [b][ch][t]
    conv_silu_t_kernel<<<dim3(DI / 32, SEQL / 32, 2), dim3(32, 8)>>>(
        p_xz, conv_w, conv_b, p_xct);

    // 4) xproj (k-split + reduce)
    xproj_part_kernel<<<dim3(TOK / 128, 8), 128>>>(p_xct, W_xproj, p_xp);
    xproj_reduce_kernel<<<(NXP * TOK + 255) / 256, 256>>>(p_xp, p_ssm);

    // 5) chunked scan
    scan_a_kernel<<<dim3(DI / 16, NCHUNK, 2), 256>>>(
        p_ssm, p_xct, A_log, W_dt, b_dt, p_P, p_hL);
    scan_b_kernel<<<(2 * DI * DS) / 256, 256>>>(p_P, p_hL, p_h0);
    scan_c_kernel<<<dim3(DI / 16, NCHUNK, 2), 256>>>(
        p_ssm, p_xct, A_log, W_dt, b_dt, Dp, p_h0, p_yt);

    // 6) gate + transpose back to [tok][ch]
    gate_kernel<<<dim3(DI / 32, SEQL / 32, 2), dim3(32, 8)>>>(p_yt, p_xz, p_y);

    // 7) out = x + y @ W_out
    gemm_mma_kernel<true><<<dim3(DM / 128, TOK / 128), 256, GSMEM>>>(
        p_y, p_WoutT, x, out, DM, DI);
}

// round 7
// speedup vs baseline: 3.7777x; 1.3547x over previous
#include <cuda_runtime.h>
#include <cuda_bf16.h>
#include <math.h>
#include <stdint.h>

// ---------------------------------------------------------------------------
// MambaBlock: B=2, S=1024, D_MODEL=1024, D_INNER=2048, D_STATE=16, D_CONV=4
// Round 7: GEMM inner loop free of cvt (tf32 HW truncation of fp32 bits),
// dt=softplus precomputed once into [b][ch][t] (removes log1pf from scans).
// ---------------------------------------------------------------------------

#define TOK 2048
#define DM  1024
#define DI  2048
#define DS  16
#define NXP 33
#define SEQL 1024
#define NCHUNK 16
#define CLEN 64   // SEQL / NCHUNK

__device__ float g_xn[TOK * DM];
__device__ float g_xz[TOK * 2 * DI];
__device__ float g_xconv_t[TOK * DI];      // [b][ch][t]
__device__ float g_ssm[TOK * NXP];
__device__ float g_dt_t[TOK * DI];         // [b][ch][t]
__device__ float g_y[TOK * DI];
__device__ float g_yt[TOK * DI];           // [b][ch][t]
__device__ float g_WinT[2 * DI * DM];
__device__ float g_WoutT[DM * DI];
__device__ float g_xp[8 * NXP * TOK];
__device__ float g_P[2 * NCHUNK * DI * DS];
__device__ float g_hL[2 * NCHUNK * DI * DS];
__device__ float g_h0[2 * NCHUNK * DI * DS];

// ------------------------------ helpers ------------------------------------
__device__ __forceinline__ uint32_t smem_u32(const void* p) {
    uint32_t a;
    asm("{ .reg .u64 t; cvta.to.shared.u64 t, %1; cvt.u32.u64 %0, t; }" : "=r"(a) : "l"(p));
    return a;
}
__device__ __forceinline__ void cp_async16(uint32_t dst, const void* src) {
    asm volatile("cp.async.cg.shared.global [%0], [%1], 16;" :: "r"(dst), "l"(src));
}
__device__ __forceinline__ void cp_commit() {
    asm volatile("cp.async.commit_group;");
}
__device__ __forceinline__ void cp_wait0() {
    asm volatile("cp.async.wait_group 0;" ::: "memory");
}
__device__ __forceinline__ void mma_tf32(float* d, const uint32_t* a, const uint32_t* b) {
    asm volatile(
        "mma.sync.aligned.m16n8k8.row.col.f32.tf32.tf32.f32 "
        "{%0,%1,%2,%3}, {%4,%5,%6,%7}, {%8,%9}, {%0,%1,%2,%3};"
        : "+f"(d[0]), "+f"(d[1]), "+f"(d[2]), "+f"(d[3])
        : "r"(a[0]), "r"(a[1]), "r"(a[2]), "r"(a[3]), "r"(b[0]), "r"(b[1]));
}
__device__ __forceinline__ float softplus_f(float x) {
    return (x > 15.f) ? x : log1pf(expf(x));
}
__device__ __forceinline__ float silu_f(float x) {
    return x / (1.f + __expf(-x));
}

// ------------------------- mma.sync tf32 GEMM ------------------------------
#define SA 36
#define ABUF (128 * SA)
#define GSMEM (4 * ABUF * 4)

template <bool RES>
__global__ void __launch_bounds__(256, 2) gemm_mma_kernel(
    const float* __restrict__ A, const float* __restrict__ Bt,
    const float* __restrict__ Rsd, float* __restrict__ C,
    int Nout, int K)
{
    extern __shared__ __align__(16) float smem[];
    float* As = smem;
    float* Bs = smem + 2 * ABUF;
    const uint32_t as_u = smem_u32(As);
    const uint32_t bs_u = smem_u32(Bs);
    const uint32_t* Asu = reinterpret_cast<const uint32_t*>(As);
    const uint32_t* Bsu = reinterpret_cast<const uint32_t*>(Bs);

    const int tid = threadIdx.x;
    const int wid = tid >> 5;
    const int lane = tid & 31;
    const int wr = wid & 3;
    const int wc = wid >> 2;
    const int g = lane >> 2;
    const int tig = lane & 3;

    const int row0 = blockIdx.y * 128;
    const int col0 = blockIdx.x * 128;
    const int KT = K >> 5;

    const int lr = tid >> 3;
    const int lc = (tid & 7) << 2;

    float acc[2][8][4];
    #pragma unroll
    for (int i = 0; i < 2; i++)
        #pragma unroll
        for (int j = 0; j < 8; j++)
            #pragma unroll
            for (int q = 0; q < 4; q++) acc[i][j][q] = 0.f;

    {
        #pragma unroll
        for (int p = 0; p < 4; ++p) {
            const int r = p * 32 + lr;
            cp_async16(as_u + (r * SA + lc) * 4, &A[(size_t)(row0 + r) * K + lc]);
            cp_async16(bs_u + (r * SA + lc) * 4, &Bt[(size_t)(col0 + r) * K + lc]);
        }
        cp_commit();
    }

    for (int i = 0; i < KT; ++i) {
        cp_wait0();
        __syncthreads();
        const int b = i & 1;
        if (i + 1 < KT) {
            const int nb = (i + 1) & 1;
            const int k0 = (i + 1) << 5;
            #pragma unroll
            for (int p = 0; p < 4; ++p) {
                const int r = p * 32 + lr;
                cp_async16(as_u + (nb * ABUF + r * SA + lc) * 4,
                           &A[(size_t)(row0 + r) * K + k0 + lc]);
                cp_async16(bs_u + (nb * ABUF + r * SA + lc) * 4,
                           &Bt[(size_t)(col0 + r) * K + k0 + lc]);
            }
            cp_commit();
        }
        const uint32_t* Ab = Asu + b * ABUF;
        const uint32_t* Bb = Bsu + b * ABUF;
        #pragma unroll
        for (int kk = 0; kk < 4; ++kk) {
            const int k = kk << 3;
            uint32_t afr[2][4];
            #pragma unroll
            for (int mt = 0; mt < 2; ++mt) {
                const int rb = wr * 32 + mt * 16;
                afr[mt][0] = Ab[(rb + g) * SA + k + tig];
                afr[mt][1] = Ab[(rb + g + 8) * SA + k + tig];
                afr[mt][2] = Ab[(rb + g) * SA + k + tig + 4];
                afr[mt][3] = Ab[(rb + g + 8) * SA + k + tig + 4];
            }
            uint32_t bfr[8][2];
            #pragma unroll
            for (int nt = 0; nt < 8; ++nt) {
                const int cb = wc * 64 + nt * 8;
                bfr[nt][0] = Bb[(cb + g) * SA + k + tig];
                bfr[nt][1] = Bb[(cb + g) * SA + k + tig + 4];
            }
            #pragma unroll
            for (int mt = 0; mt < 2; ++mt)
                #pragma unroll
                for (int nt = 0; nt < 8; ++nt)
                    mma_tf32(acc[mt][nt], afr[mt], bfr[nt]);
        }
        __syncthreads();
    }

    #pragma unroll
    for (int mt = 0; mt < 2; ++mt) {
        const int r0 = row0 + wr * 32 + mt * 16 + g;
        #pragma unroll
        for (int nt = 0; nt < 8; ++nt) {
            const int c = col0 + wc * 64 + nt * 8 + tig * 2;
            float2 v0 = make_float2(acc[mt][nt][0], acc[mt][nt][1]);
            float2 v1 = make_float2(acc[mt][nt][2], acc[mt][nt][3]);
            if (RES) {
                float2 r0v = *reinterpret_cast<const float2*>(&Rsd[(size_t)r0 * Nout + c]);
                float2 r1v = *reinterpret_cast<const float2*>(&Rsd[(size_t)(r0 + 8) * Nout + c]);
                v0.x += r0v.x; v0.y += r0v.y;
                v1.x += r1v.x; v1.y += r1v.y;
            }
            *reinterpret_cast<float2*>(&C[(size_t)r0 * Nout + c]) = v0;
            *reinterpret_cast<float2*>(&C[(size_t)(r0 + 8) * Nout + c]) = v1;
        }
    }
}

// ------------------------------ transpose ----------------------------------
__global__ void __launch_bounds__(256) transpose_kernel(
    const float* __restrict__ in, float* __restrict__ out, int R, int Ccols)
{
    __shared__ float tile[32][33];
    const int c0 = blockIdx.x * 32, r0 = blockIdx.y * 32;
    const int x = threadIdx.x, y = threadIdx.y;
    #pragma unroll
    for (int j = 0; j < 32; j += 8)
        tile[y + j][x] = in[(size_t)(r0 + y + j) * Ccols + c0 + x];
    __syncthreads();
    #pragma unroll
    for (int j = 0; j < 32; j += 8)
        out[(size_t)(c0 + y + j) * R + r0 + x] = tile[x][y + j];
}

// ------------------------------ rmsnorm ------------------------------------
__global__ void __launch_bounds__(256) rmsnorm_kernel(
    const float* __restrict__ x, const float* __restrict__ w, float* __restrict__ xn)
{
    const int token = blockIdx.x;
    const int tid = threadIdx.x;
    const float4* x4 = reinterpret_cast<const float4*>(x + (size_t)token * DM);
    float4 v = x4[tid];
    float s = v.x * v.x + v.y * v.y + v.z * v.z + v.w * v.w;
    __shared__ float red[8];
    #pragma unroll
    for (int o = 16; o; o >>= 1) s += __shfl_xor_sync(0xffffffffu, s, o);
    if ((tid & 31) == 0) red[tid >> 5] = s;
    __syncthreads();
    if (tid < 32) {
        float t = (tid < 8) ? red[tid] : 0.f;
        #pragma unroll
        for (int o = 4; o; o >>= 1) t += __shfl_xor_sync(0xffffffffu, t, o);
        if (tid == 0) red[0] = t;
    }
    __syncthreads();
    const float ms = red[0] * (1.f / (float)DM);
    const float r = rsqrtf(ms + 1.1920928955078125e-07f);
    const float4* w4 = reinterpret_cast<const float4*>(w);
    float4 wv = w4[tid];
    float4 o;
    o.x = v.x * r * wv.x; o.y = v.y * r * wv.y;
    o.z = v.z * r * wv.z; o.w = v.w * r * wv.w;
    reinterpret_cast<float4*>(xn + (size_t)token * DM)[tid] = o;
}

// ------------- causal depthwise conv + silu, transposed output -------------
__global__ void __launch_bounds__(256) conv_silu_t_kernel(
    const float* __restrict__ xz, const float* __restrict__ cw,
    const float* __restrict__ cb, float* __restrict__ xconv_t)
{
    __shared__ float tile[35][33];
    const int ch0 = blockIdx.x * 32;
    const int t0 = blockIdx.y * 32;
    const int b = blockIdx.z;
    const int tx = threadIdx.x, ty = threadIdx.y;

    for (int j = ty; j < 35; j += 8) {
        const int tg = t0 + j - 3;
        tile[j][tx] = (tg >= 0) ? xz[(size_t)(b * SEQL + tg) * (2 * DI) + ch0 + tx] : 0.f;
    }
    __syncthreads();

    #pragma unroll
    for (int q = 0; q < 4; ++q) {
        const int chl = ty + q * 8;
        const int ch = ch0 + chl;
        float acc = cb[ch];
        #pragma unroll
        for (int k = 0; k < 4; ++k)
            acc = fmaf(tile[tx + k][chl], cw[ch * 4 + k], acc);
        xconv_t[((size_t)b * DI + ch) * SEQL + t0 + tx] = silu_f(acc);
    }
}

// ---------------------- xproj partials (k-split) ---------------------------
__global__ void __launch_bounds__(128) xproj_part_kernel(
    const float* __restrict__ xconv_t, const float* __restrict__ W,
    float* __restrict__ part)
{
    __shared__ float Wbuf[64][NXP];
    const int tok = blockIdx.x * 128 + threadIdx.x;
    const int b = tok >> 10;
    const int t = tok & (SEQL - 1);
    const int ks = blockIdx.y;
    const int kbase = ks * (DI / 8);

    float acc[NXP];
    #pragma unroll
    for (int c = 0; c < NXP; ++c) acc[c] = 0.f;

    for (int kc = 0; kc < DI / 8; kc += 64) {
        __syncthreads();
        for (int i = threadIdx.x; i < 64 * NXP; i += 128) {
            const int kr = i / NXP, c = i - kr * NXP;
            Wbuf[kr][c] = W[(size_t)(kbase + kc + kr) * NXP + c];
        }
        __syncthreads();
        #pragma unroll 4
        for (int kr = 0; kr < 64; ++kr) {
            const float xv = xconv_t[((size_t)b * DI + kbase + kc + kr) * SEQL + t];
            #pragma unroll
            for (int c = 0; c < NXP; ++c)
                acc[c] = fmaf(xv, Wbuf[kr][c], acc[c]);
        }
    }
    #pragma unroll
    for (int c = 0; c < NXP; ++c)
        part[((size_t)ks * NXP + c) * TOK + tok] = acc[c];
}

__global__ void __launch_bounds__(256) xproj_reduce_kernel(
    const float* __restrict__ part, float* __restrict__ ssm)
{
    const int idx = blockIdx.x * 256 + threadIdx.x;
    if (idx >= NXP * TOK) return;
    const int c = idx / TOK;
    const int tok = idx - c * TOK;
    float s = 0.f;
    #pragma unroll
    for (int ks = 0; ks < 8; ++ks)
        s += part[((size_t)ks * NXP + c) * TOK + tok];
    ssm[(size_t)tok * NXP + c] = s;
}

// ------------------------- dt precompute -----------------------------------
// dt_t[b][ch][t] = softplus(ssm[tok,0]*W_dt[ch] + b_dt[ch]).
// block(32,8): 32 t x 64 ch.  grid(DI/64, SEQL/32, 2)
__global__ void __launch_bounds__(256) dt_t_kernel(
    const float* __restrict__ ssm, const float* __restrict__ W_dt,
    const float* __restrict__ b_dt, float* __restrict__ dt_t)
{
    __shared__ float sdt[32];
    const int ch0 = blockIdx.x * 64;
    const int t0 = blockIdx.y * 32;
    const int b = blockIdx.z;
    const int tx = threadIdx.x, ty = threadIdx.y;
    if (ty == 0)
        sdt[tx] = ssm[(size_t)(b * SEQL + t0 + tx) * NXP];
    __syncthreads();
    const float dtr = sdt[tx];
    #pragma unroll
    for (int q = 0; q < 8; ++q) {
        const int ch = ch0 + ty + q * 8;
        const float xv = fmaf(dtr, W_dt[ch], b_dt[ch]);
        dt_t[((size_t)b * DI + ch) * SEQL + t0 + tx] = softplus_f(xv);
    }
}

// --------------------------- scan phase A ----------------------------------
__global__ void __launch_bounds__(256) scan_a_kernel(
    const float* __restrict__ ssm, const float* __restrict__ xconv_t,
    const float* __restrict__ dt_t, const float* __restrict__ A_log,
    float* __restrict__ Pout, float* __restrict__ hLout)
{
    const int lane = threadIdx.x & 31;
    const int warp = threadIdx.x >> 5;
    const int n = lane & 15;
    const int half = lane >> 4;
    const int ch = blockIdx.x * 16 + warp * 2 + half;
    const int chunk = blockIdx.y;
    const int b = blockIdx.z;

    const float An = -expf(A_log[ch * DS + n]);

    const float* srow = ssm + (size_t)(b * SEQL + chunk * CLEN) * NXP;
    const float* xc = xconv_t + ((size_t)b * DI + ch) * SEQL + chunk * CLEN;
    const float* dtp = dt_t + ((size_t)b * DI + ch) * SEQL + chunk * CLEN;

    float h = 0.f, P = 1.f;
    #pragma unroll 4
    for (int t = 0; t < CLEN; ++t) {
        const float Bv = srow[1 + n];
        const float dtv = dtp[t];
        const float ab = __expf(dtv * An);
        h = fmaf(ab, h, dtv * xc[t] * Bv);
        P *= ab;
        srow += NXP;
    }
    const size_t idx = (((size_t)b * NCHUNK + chunk) * DI + ch) * DS + n;
    Pout[idx] = P;
    hLout[idx] = h;
}

// --------------------------- scan phase B ----------------------------------
__global__ void __launch_bounds__(256) scan_b_kernel(
    const float* __restrict__ P, const float* __restrict__ hL,
    float* __restrict__ h0)
{
    const int gid = blockIdx.x * 256 + threadIdx.x;
    const int b = gid / (DI * DS);
    const int r = gid - b * (DI * DS);
    float h = 0.f;
    #pragma unroll
    for (int c = 0; c < NCHUNK; ++c) {
        const size_t idx = ((size_t)(b * NCHUNK + c)) * (DI * DS) + r;
        h0[idx] = h;
        h = fmaf(P[idx], h, hL[idx]);
    }
}

// --------------------------- scan phase C ----------------------------------
__global__ void __launch_bounds__(256) scan_c_kernel(
    const float* __restrict__ ssm, const float* __restrict__ xconv_t,
    const float* __restrict__ dt_t, const float* __restrict__ A_log,
    const float* __restrict__ Dp, const float* __restrict__ h0,
    float* __restrict__ yt)
{
    const int lane = threadIdx.x & 31;
    const int warp = threadIdx.x >> 5;
    const int n = lane & 15;
    const int half = lane >> 4;
    const int ch = blockIdx.x * 16 + warp * 2 + half;
    const int chunk = blockIdx.y;
    const int b = blockIdx.z;

    const float An = -expf(A_log[ch * DS + n]);
    const float Dch = Dp[ch];

    const float* srow = ssm + (size_t)(b * SEQL + chunk * CLEN) * NXP;
    const float* xc = xconv_t + ((size_t)b * DI + ch) * SEQL + chunk * CLEN;
    const float* dtp = dt_t + ((size_t)b * DI + ch) * SEQL + chunk * CLEN;
    float* yrow = yt + ((size_t)b * DI + ch) * SEQL + chunk * CLEN;

    float h = h0[(((size_t)b * NCHUNK + chunk) * DI + ch) * DS + n];

    #pragma unroll 4
    for (int t = 0; t < CLEN; ++t) {
        const float Bv = srow[1 + n];
        const float Cv = srow[1 + DS + n];
        const float xcv = xc[t];
        const float dtv = dtp[t];
        const float ab = __expf(dtv * An);
        h = fmaf(ab, h, dtv * xcv * Bv);
        float p = h * Cv;
        p += __shfl_xor_sync(0xffffffffu, p, 1);
        p += __shfl_xor_sync(0xffffffffu, p, 2);
        p += __shfl_xor_sync(0xffffffffu, p, 4);
        p += __shfl_xor_sync(0xffffffffu, p, 8);
        if (n == 0) yrow[t] = fmaf(xcv, Dch, p);
        srow += NXP;
    }
}

// ------------------------- gate + transpose --------------------------------
__global__ void __launch_bounds__(256) gate_kernel(
    const float* __restrict__ yt, const float* __restrict__ xz,
    float* __restrict__ y)
{
    __shared__ float tile[32][33];
    const int ch0 = blockIdx.x * 32;
    const int t0 = blockIdx.y * 32;
    const int b = blockIdx.z;
    const int tx = threadIdx.x, ty = threadIdx.y;
    #pragma unroll
    for (int j = 0; j < 32; j += 8)
        tile[ty + j][tx] = yt[((size_t)b * DI + ch0 + ty + j) * SEQL + t0 + tx];
    __syncthreads();
    #pragma unroll
    for (int j = 0; j < 32; j += 8) {
        const int tok = b * SEQL + t0 + ty + j;
        const float z = xz[(size_t)tok * (2 * DI) + DI + ch0 + tx];
        y[(size_t)tok * DI + ch0 + tx] = tile[tx][ty + j] * silu_f(z);
    }
}

// ---------------------------------------------------------------------------
extern "C" void kernel_launch(void* const* d_in, const int* in_sizes, int n_in,
                              void* d_out, int out_size)
{
    const float* x      = (const float*)d_in[0];
    const float* W_in   = (const float*)d_in[1];
    const float* conv_w = (const float*)d_in[2];
    const float* conv_b = (const float*)d_in[3];
    const float* W_xproj= (const float*)d_in[4];
    const float* W_dt   = (const float*)d_in[5];
    const float* b_dt   = (const float*)d_in[6];
    const float* A_log  = (const float*)d_in[7];
    const float* Dp     = (const float*)d_in[8];
    const float* W_out  = (const float*)d_in[9];
    const float* norm_w = (const float*)d_in[10];
    float* out = (float*)d_out;

    float *p_xn, *p_xz, *p_xct, *p_ssm, *p_dtt, *p_y, *p_yt, *p_WinT, *p_WoutT;
    float *p_xp, *p_P, *p_hL, *p_h0;
    cudaGetSymbolAddress((void**)&p_xn, g_xn);
    cudaGetSymbolAddress((void**)&p_xz, g_xz);
    cudaGetSymbolAddress((void**)&p_xct, g_xconv_t);
    cudaGetSymbolAddress((void**)&p_ssm, g_ssm);
    cudaGetSymbolAddress((void**)&p_dtt, g_dt_t);
    cudaGetSymbolAddress((void**)&p_y, g_y);
    cudaGetSymbolAddress((void**)&p_yt, g_yt);
    cudaGetSymbolAddress((void**)&p_WinT, g_WinT);
    cudaGetSymbolAddress((void**)&p_WoutT, g_WoutT);
    cudaGetSymbolAddress((void**)&p_xp, g_xp);
    cudaGetSymbolAddress((void**)&p_P, g_P);
    cudaGetSymbolAddress((void**)&p_hL, g_hL);
    cudaGetSymbolAddress((void**)&p_h0, g_h0);

    static bool attr_done = false;
    if (!attr_done) {
        cudaFuncSetAttribute(gemm_mma_kernel<false>,
                             cudaFuncAttributeMaxDynamicSharedMemorySize, GSMEM);
        cudaFuncSetAttribute(gemm_mma_kernel<true>,
                             cudaFuncAttributeMaxDynamicSharedMemorySize, GSMEM);
        attr_done = true;
    }

    transpose_kernel<<<dim3((2 * DI) / 32, DM / 32), dim3(32, 8)>>>(W_in, p_WinT, DM, 2 * DI);
    transpose_kernel<<<dim3(DM / 32, DI / 32), dim3(32, 8)>>>(W_out, p_WoutT, DI, DM);

    rmsnorm_kernel<<<TOK, 256>>>(x, norm_w, p_xn);

    gemm_mma_kernel<false><<<dim3((2 * DI) / 128, TOK / 128), 256, GSMEM>>>(
        p_xn, p_WinT, nullptr, p_xz, 2 * DI, DM);

    conv_silu_t_kernel<<<dim3(DI / 32, SEQL / 32, 2), dim3(32, 8)>>>(
        p_xz, conv_w, conv_b, p_xct);

    xproj_part_kernel<<<dim3(TOK / 128, 8), 128>>>(p_xct, W_xproj, p_xp);
    xproj_reduce_kernel<<<(NXP * TOK + 255) / 256, 256>>>(p_xp, p_ssm);

    dt_t_kernel<<<dim3(DI / 64, SEQL / 32, 2), dim3(32, 8)>>>(
        p_ssm, W_dt, b_dt, p_dtt);

    scan_a_kernel<<<dim3(DI / 16, NCHUNK, 2), 256>>>(
        p_ssm, p_xct, p_dtt, A_log, p_P, p_hL);
    scan_b_kernel<<<(2 * DI * DS) / 256, 256>>>(p_P, p_hL, p_h0);
    scan_c_kernel<<<dim3(DI / 16, NCHUNK, 2), 256>>>(
        p_ssm, p_xct, p_dtt, A_log, Dp, p_h0, p_yt);

    gate_kernel<<<dim3(DI / 32, SEQL / 32, 2), dim3(32, 8)>>>(p_yt, p_xz, p_y);

    gemm_mma_kernel<true><<<dim3(DM / 128, TOK / 128), 256, GSMEM>>>(
        p_y, p_WoutT, x, out, DM, DI);
}

// round 10
// speedup vs baseline: 3.8043x; 1.0070x over previous
#include <cuda_runtime.h>
#include <cuda_bf16.h>
#include <math.h>
#include <stdint.h>

// ---------------------------------------------------------------------------
// MambaBlock: B=2, S=1024, D_MODEL=1024, D_INNER=2048, D_STATE=16, D_CONV=4
// Round 8: GEMM consumes weights native [K,N] (no transposes), 3-stage
// cp.async pipeline (1 sync/iter); fused single-kernel chunked scan
// (phaseA + combine + phaseC in-block, L1-hot phase C).
// ---------------------------------------------------------------------------

#define TOK 2048
#define DM  1024
#define DI  2048
#define DS  16
#define NXP 33
#define SEQL 1024
#define NCHUNK 16
#define CLEN 64

__device__ float g_xn[TOK * DM];
__device__ float g_xz[TOK * 2 * DI];
__device__ float g_xconv_t[TOK * DI];      // [b][ch][t]
__device__ float g_ssm[TOK * NXP];
__device__ float g_dt_t[TOK * DI];         // [b][ch][t]
__device__ float g_y[TOK * DI];
__device__ float g_yt[TOK * DI];           // [b][ch][t]
__device__ float g_xp[8 * NXP * TOK];

// ------------------------------ helpers ------------------------------------
__device__ __forceinline__ uint32_t smem_u32(const void* p) {
    uint32_t a;
    asm("{ .reg .u64 t; cvta.to.shared.u64 t, %1; cvt.u32.u64 %0, t; }" : "=r"(a) : "l"(p));
    return a;
}
__device__ __forceinline__ void cp_async16(uint32_t dst, const void* src) {
    asm volatile("cp.async.cg.shared.global [%0], [%1], 16;" :: "r"(dst), "l"(src));
}
__device__ __forceinline__ void cp_commit() {
    asm volatile("cp.async.commit_group;");
}
__device__ __forceinline__ void mma_tf32(float* d, const uint32_t* a, const uint32_t* b) {
    asm volatile(
        "mma.sync.aligned.m16n8k8.row.col.f32.tf32.tf32.f32 "
        "{%0,%1,%2,%3}, {%4,%5,%6,%7}, {%8,%9}, {%0,%1,%2,%3};"
        : "+f"(d[0]), "+f"(d[1]), "+f"(d[2]), "+f"(d[3])
        : "r"(a[0]), "r"(a[1]), "r"(a[2]), "r"(a[3]), "r"(b[0]), "r"(b[1]));
}
__device__ __forceinline__ float softplus_f(float x) {
    return (x > 15.f) ? x : log1pf(expf(x));
}
__device__ __forceinline__ float silu_f(float x) {
    return x / (1.f + __expf(-x));
}

// ------------------------- mma.sync tf32 GEMM ------------------------------
// C[M,N] = A[M,K] @ B[K,N] (+ Rsd).  B consumed in NATIVE [K,N] layout.
// 3-stage cp.async pipeline, 1 __syncthreads per ktile.
#define SAq 36
#define SBq 136
#define ATILEF (128 * SAq)   // 4608 floats
#define BTILEF (32 * SBq)    // 4352 floats
#define GSMEM (3 * (ATILEF + BTILEF) * 4)

template <bool RES>
__global__ void __launch_bounds__(256, 2) gemm_mma_kernel(
    const float* __restrict__ A, const float* __restrict__ B,
    const float* __restrict__ Rsd, float* __restrict__ C,
    int Nout, int K)
{
    extern __shared__ __align__(16) float smem[];
    float* As = smem;                  // 3 stages
    float* Bs = smem + 3 * ATILEF;     // 3 stages
    const uint32_t as_u = smem_u32(As);
    const uint32_t bs_u = smem_u32(Bs);

    const int tid = threadIdx.x;
    const int wid = tid >> 5;
    const int lane = tid & 31;
    const int wr = wid & 3;
    const int wc = wid >> 2;
    const int g = lane >> 2;
    const int tig = lane & 3;

    const int row0 = blockIdx.y * 128;
    const int col0 = blockIdx.x * 128;
    const int KT = K >> 5;

    const int alr = tid >> 3;
    const int alc = (tid & 7) << 2;
    const int blr = tid >> 5;
    const int blc = (tid & 31) << 2;

    float acc[2][8][4];
    #pragma unroll
    for (int i = 0; i < 2; i++)
        #pragma unroll
        for (int j = 0; j < 8; j++)
            #pragma unroll
            for (int q = 0; q < 4; q++) acc[i][j][q] = 0.f;

    // stage loader
    auto load_stage = [&](int i, int s) {
        const int k0 = i << 5;
        #pragma unroll
        for (int p = 0; p < 4; ++p) {
            const int r = p * 32 + alr;
            cp_async16(as_u + (s * ATILEF + r * SAq + alc) * 4,
                       &A[(size_t)(row0 + r) * K + k0 + alc]);
        }
        #pragma unroll
        for (int p = 0; p < 4; ++p) {
            const int kr = p * 8 + blr;
            cp_async16(bs_u + (s * BTILEF + kr * SBq + blc) * 4,
                       &B[(size_t)(k0 + kr) * Nout + col0 + blc]);
        }
    };

    load_stage(0, 0); cp_commit();
    load_stage(1, 1); cp_commit();

    for (int i = 0; i < KT; ++i) {
        asm volatile("cp.async.wait_group 1;" ::: "memory");
        __syncthreads();
        if (i + 2 < KT) load_stage(i + 2, (i + 2) % 3);
        cp_commit();   // uniform commits keep the wait_group-1 invariant in the tail

        const uint32_t* Ab = reinterpret_cast<const uint32_t*>(As + (i % 3) * ATILEF);
        const uint32_t* Bb = reinterpret_cast<const uint32_t*>(Bs + (i % 3) * BTILEF);
        #pragma unroll
        for (int kk = 0; kk < 4; ++kk) {
            const int k = kk << 3;
            uint32_t afr[2][4];
            #pragma unroll
            for (int mt = 0; mt < 2; ++mt) {
                const int rb = wr * 32 + mt * 16;
                afr[mt][0] = Ab[(rb + g) * SAq + k + tig];
                afr[mt][1] = Ab[(rb + g + 8) * SAq + k + tig];
                afr[mt][2] = Ab[(rb + g) * SAq + k + tig + 4];
                afr[mt][3] = Ab[(rb + g + 8) * SAq + k + tig + 4];
            }
            uint32_t bfr[8][2];
            #pragma unroll
            for (int nt = 0; nt < 8; ++nt) {
                const int cb = wc * 64 + nt * 8 + g;
                bfr[nt][0] = Bb[(k + tig) * SBq + cb];
                bfr[nt][1] = Bb[(k + tig + 4) * SBq + cb];
            }
            #pragma unroll
            for (int mt = 0; mt < 2; ++mt)
                #pragma unroll
                for (int nt = 0; nt < 8; ++nt)
                    mma_tf32(acc[mt][nt], afr[mt], bfr[nt]);
        }
    }

    #pragma unroll
    for (int mt = 0; mt < 2; ++mt) {
        const int r0 = row0 + wr * 32 + mt * 16 + g;
        #pragma unroll
        for (int nt = 0; nt < 8; ++nt) {
            const int c = col0 + wc * 64 + nt * 8 + tig * 2;
            float2 v0 = make_float2(acc[mt][nt][0], acc[mt][nt][1]);
            float2 v1 = make_float2(acc[mt][nt][2], acc[mt][nt][3]);
            if (RES) {
                float2 r0v = *reinterpret_cast<const float2*>(&Rsd[(size_t)r0 * Nout + c]);
                float2 r1v = *reinterpret_cast<const float2*>(&Rsd[(size_t)(r0 + 8) * Nout + c]);
                v0.x += r0v.x; v0.y += r0v.y;
                v1.x += r1v.x; v1.y += r1v.y;
            }
            *reinterpret_cast<float2*>(&C[(size_t)r0 * Nout + c]) = v0;
            *reinterpret_cast<float2*>(&C[(size_t)(r0 + 8) * Nout + c]) = v1;
        }
    }
}

// ------------------------------ rmsnorm ------------------------------------
__global__ void __launch_bounds__(256) rmsnorm_kernel(
    const float* __restrict__ x, const float* __restrict__ w, float* __restrict__ xn)
{
    const int token = blockIdx.x;
    const int tid = threadIdx.x;
    const float4* x4 = reinterpret_cast<const float4*>(x + (size_t)token * DM);
    float4 v = x4[tid];
    float s = v.x * v.x + v.y * v.y + v.z * v.z + v.w * v.w;
    __shared__ float red[8];
    #pragma unroll
    for (int o = 16; o; o >>= 1) s += __shfl_xor_sync(0xffffffffu, s, o);
    if ((tid & 31) == 0) red[tid >> 5] = s;
    __syncthreads();
    if (tid < 32) {
        float t = (tid < 8) ? red[tid] : 0.f;
        #pragma unroll
        for (int o = 4; o; o >>= 1) t += __shfl_xor_sync(0xffffffffu, t, o);
        if (tid == 0) red[0] = t;
    }
    __syncthreads();
    const float ms = red[0] * (1.f / (float)DM);
    const float r = rsqrtf(ms + 1.1920928955078125e-07f);
    const float4* w4 = reinterpret_cast<const float4*>(w);
    float4 wv = w4[tid];
    float4 o;
    o.x = v.x * r * wv.x; o.y = v.y * r * wv.y;
    o.z = v.z * r * wv.z; o.w = v.w * r * wv.w;
    reinterpret_cast<float4*>(xn + (size_t)token * DM)[tid] = o;
}

// ------------- causal depthwise conv + silu, transposed output -------------
__global__ void __launch_bounds__(256) conv_silu_t_kernel(
    const float* __restrict__ xz, const float* __restrict__ cw,
    const float* __restrict__ cb, float* __restrict__ xconv_t)
{
    __shared__ float tile[35][33];
    const int ch0 = blockIdx.x * 32;
    const int t0 = blockIdx.y * 32;
    const int b = blockIdx.z;
    const int tx = threadIdx.x, ty = threadIdx.y;

    for (int j = ty; j < 35; j += 8) {
        const int tg = t0 + j - 3;
        tile[j][tx] = (tg >= 0) ? xz[(size_t)(b * SEQL + tg) * (2 * DI) + ch0 + tx] : 0.f;
    }
    __syncthreads();

    #pragma unroll
    for (int q = 0; q < 4; ++q) {
        const int chl = ty + q * 8;
        const int ch = ch0 + chl;
        float acc = cb[ch];
        #pragma unroll
        for (int k = 0; k < 4; ++k)
            acc = fmaf(tile[tx + k][chl], cw[ch * 4 + k], acc);
        xconv_t[((size_t)b * DI + ch) * SEQL + t0 + tx] = silu_f(acc);
    }
}

// ---------------------- xproj partials (k-split) ---------------------------
__global__ void __launch_bounds__(128) xproj_part_kernel(
    const float* __restrict__ xconv_t, const float* __restrict__ W,
    float* __restrict__ part)
{
    __shared__ float Wbuf[64][NXP];
    const int tok = blockIdx.x * 128 + threadIdx.x;
    const int b = tok >> 10;
    const int t = tok & (SEQL - 1);
    const int ks = blockIdx.y;
    const int kbase = ks * (DI / 8);

    float acc[NXP];
    #pragma unroll
    for (int c = 0; c < NXP; ++c) acc[c] = 0.f;

    for (int kc = 0; kc < DI / 8; kc += 64) {
        __syncthreads();
        for (int i = threadIdx.x; i < 64 * NXP; i += 128) {
            const int kr = i / NXP, c = i - kr * NXP;
            Wbuf[kr][c] = W[(size_t)(kbase + kc + kr) * NXP + c];
        }
        __syncthreads();
        #pragma unroll 4
        for (int kr = 0; kr < 64; ++kr) {
            const float xv = xconv_t[((size_t)b * DI + kbase + kc + kr) * SEQL + t];
            #pragma unroll
            for (int c = 0; c < NXP; ++c)
                acc[c] = fmaf(xv, Wbuf[kr][c], acc[c]);
        }
    }
    #pragma unroll
    for (int c = 0; c < NXP; ++c)
        part[((size_t)ks * NXP + c) * TOK + tok] = acc[c];
}

__global__ void __launch_bounds__(256) xproj_reduce_kernel(
    const float* __restrict__ part, float* __restrict__ ssm)
{
    const int idx = blockIdx.x * 256 + threadIdx.x;
    if (idx >= NXP * TOK) return;
    const int c = idx / TOK;
    const int tok = idx - c * TOK;
    float s = 0.f;
    #pragma unroll
    for (int ks = 0; ks < 8; ++ks)
        s += part[((size_t)ks * NXP + c) * TOK + tok];
    ssm[(size_t)tok * NXP + c] = s;
}

// ------------------------- dt precompute -----------------------------------
__global__ void __launch_bounds__(256) dt_t_kernel(
    const float* __restrict__ ssm, const float* __restrict__ W_dt,
    const float* __restrict__ b_dt, float* __restrict__ dt_t)
{
    __shared__ float sdt[32];
    const int ch0 = blockIdx.x * 64;
    const int t0 = blockIdx.y * 32;
    const int b = blockIdx.z;
    const int tx = threadIdx.x, ty = threadIdx.y;
    if (ty == 0)
        sdt[tx] = ssm[(size_t)(b * SEQL + t0 + tx) * NXP];
    __syncthreads();
    const float dtr = sdt[tx];
    #pragma unroll
    for (int q = 0; q < 8; ++q) {
        const int ch = ch0 + ty + q * 8;
        const float xv = fmaf(dtr, W_dt[ch], b_dt[ch]);
        dt_t[((size_t)b * DI + ch) * SEQL + t0 + tx] = softplus_f(xv);
    }
}

// --------------------------- fused scan ------------------------------------
// Block = one (b, ch). 8 warps = 16 half-warps = 16 chunks; lane n = state.
// Phase A (local scan + decay product) -> smem combine -> phase C (L1-hot).
__global__ void __launch_bounds__(256) scan_fused_kernel(
    const float* __restrict__ ssm, const float* __restrict__ xconv_t,
    const float* __restrict__ dt_t, const float* __restrict__ A_log,
    const float* __restrict__ Dp, float* __restrict__ yt)
{
    __shared__ float sP[NCHUNK][DS];
    __shared__ float shL[NCHUNK][DS];
    __shared__ float sh0[NCHUNK][DS];
    __shared__ float sy[SEQL];

    const int ch = blockIdx.x;
    const int b = blockIdx.y;
    const int lane = threadIdx.x & 31;
    const int warp = threadIdx.x >> 5;
    const int n = lane & 15;
    const int chunk = warp * 2 + (lane >> 4);

    const float An = -expf(A_log[ch * DS + n]);
    const float Dch = Dp[ch];

    const float* srow0 = ssm + (size_t)(b * SEQL + chunk * CLEN) * NXP;
    const float* xc = xconv_t + ((size_t)b * DI + ch) * SEQL + chunk * CLEN;
    const float* dtp = dt_t + ((size_t)b * DI + ch) * SEQL + chunk * CLEN;

    // phase A: local scan with h0 = 0, track decay product
    {
        float h = 0.f, P = 1.f;
        const float* sr = srow0;
        #pragma unroll 4
        for (int t = 0; t < CLEN; ++t) {
            const float Bv = sr[1 + n];
            const float dtv = dtp[t];
            const float ab = __expf(dtv * An);
            h = fmaf(ab, h, dtv * xc[t] * Bv);
            P *= ab;
            sr += NXP;
        }
        sP[chunk][n] = P;
        shL[chunk][n] = h;
    }
    __syncthreads();

    // combine: 16 threads, one per n, serial over chunks
    if (threadIdx.x < DS) {
        const int nn = threadIdx.x;
        float h = 0.f;
        #pragma unroll
        for (int c = 0; c < NCHUNK; ++c) {
            sh0[c][nn] = h;
            h = fmaf(sP[c][nn], h, shL[c][nn]);
        }
    }
    __syncthreads();

    // phase C: replay with correct h0 (loads L1-hot), emit y into smem
    {
        float h = sh0[chunk][n];
        const float* sr = srow0;
        #pragma unroll 4
        for (int t = 0; t < CLEN; ++t) {
            const float Bv = sr[1 + n];
            const float Cv = sr[1 + DS + n];
            const float xcv = xc[t];
            const float dtv = dtp[t];
            const float ab = __expf(dtv * An);
            h = fmaf(ab, h, dtv * xcv * Bv);
            float p = h * Cv;
            p += __shfl_xor_sync(0xffffffffu, p, 1);
            p += __shfl_xor_sync(0xffffffffu, p, 2);
            p += __shfl_xor_sync(0xffffffffu, p, 4);
            p += __shfl_xor_sync(0xffffffffu, p, 8);
            if (n == 0) sy[chunk * CLEN + t] = fmaf(xcv, Dch, p);
            sr += NXP;
        }
    }
    __syncthreads();

    // coalesced row write
    float* yrow = yt + ((size_t)b * DI + ch) * SEQL;
    for (int i = threadIdx.x; i < SEQL; i += 256)
        yrow[i] = sy[i];
}

// ------------------------- gate + transpose --------------------------------
__global__ void __launch_bounds__(256) gate_kernel(
    const float* __restrict__ yt, const float* __restrict__ xz,
    float* __restrict__ y)
{
    __shared__ float tile[32][33];
    const int ch0 = blockIdx.x * 32;
    const int t0 = blockIdx.y * 32;
    const int b = blockIdx.z;
    const int tx = threadIdx.x, ty = threadIdx.y;
    #pragma unroll
    for (int j = 0; j < 32; j += 8)
        tile[ty + j][tx] = yt[((size_t)b * DI + ch0 + ty + j) * SEQL + t0 + tx];
    __syncthreads();
    #pragma unroll
    for (int j = 0; j < 32; j += 8) {
        const int tok = b * SEQL + t0 + ty + j;
        const float z = xz[(size_t)tok * (2 * DI) + DI + ch0 + tx];
        y[(size_t)tok * DI + ch0 + tx] = tile[tx][ty + j] * silu_f(z);
    }
}

// ---------------------------------------------------------------------------
extern "C" void kernel_launch(void* const* d_in, const int* in_sizes, int n_in,
                              void* d_out, int out_size)
{
    const float* x      = (const float*)d_in[0];
    const float* W_in   = (const float*)d_in[1];
    const float* conv_w = (const float*)d_in[2];
    const float* conv_b = (const float*)d_in[3];
    const float* W_xproj= (const float*)d_in[4];
    const float* W_dt   = (const float*)d_in[5];
    const float* b_dt   = (const float*)d_in[6];
    const float* A_log  = (const float*)d_in[7];
    const float* Dp     = (const float*)d_in[8];
    const float* W_out  = (const float*)d_in[9];
    const float* norm_w = (const float*)d_in[10];
    float* out = (float*)d_out;

    float *p_xn, *p_xz, *p_xct, *p_ssm, *p_dtt, *p_y, *p_yt, *p_xp;
    cudaGetSymbolAddress((void**)&p_xn, g_xn);
    cudaGetSymbolAddress((void**)&p_xz, g_xz);
    cudaGetSymbolAddress((void**)&p_xct, g_xconv_t);
    cudaGetSymbolAddress((void**)&p_ssm, g_ssm);
    cudaGetSymbolAddress((void**)&p_dtt, g_dt_t);
    cudaGetSymbolAddress((void**)&p_y, g_y);
    cudaGetSymbolAddress((void**)&p_yt, g_yt);
    cudaGetSymbolAddress((void**)&p_xp, g_xp);

    static bool attr_done = false;
    if (!attr_done) {
        cudaFuncSetAttribute(gemm_mma_kernel<false>,
                             cudaFuncAttributeMaxDynamicSharedMemorySize, GSMEM);
        cudaFuncSetAttribute(gemm_mma_kernel<true>,
                             cudaFuncAttributeMaxDynamicSharedMemorySize, GSMEM);
        attr_done = true;
    }

    // 1) rmsnorm
    rmsnorm_kernel<<<TOK, 256>>>(x, norm_w, p_xn);

    // 2) xz = xn @ W_in   (W_in native [K=1024, N=4096])
    gemm_mma_kernel<false><<<dim3((2 * DI) / 128, TOK / 128), 256, GSMEM>>>(
        p_xn, W_in, nullptr, p_xz, 2 * DI, DM);

    // 3) conv + silu -> [b][ch][t]
    conv_silu_t_kernel<<<dim3(DI / 32, SEQL / 32, 2), dim3(32, 8)>>>(
        p_xz, conv_w, conv_b, p_xct);

    // 4) xproj
    xproj_part_kernel<<<dim3(TOK / 128, 8), 128>>>(p_xct, W_xproj, p_xp);
    xproj_reduce_kernel<<<(NXP * TOK + 255) / 256, 256>>>(p_xp, p_ssm);

    // 5) dt precompute
    dt_t_kernel<<<dim3(DI / 64, SEQL / 32, 2), dim3(32, 8)>>>(
        p_ssm, W_dt, b_dt, p_dtt);

    // 6) fused chunked scan
    scan_fused_kernel<<<dim3(DI, 2), 256>>>(
        p_ssm, p_xct, p_dtt, A_log, Dp, p_yt);

    // 7) gate + transpose back
    gate_kernel<<<dim3(DI / 32, SEQL / 32, 2), dim3(32, 8)>>>(p_yt, p_xz, p_y);

    // 8) out = x + y @ W_out   (W_out native [K=2048, N=1024])
    gemm_mma_kernel<true><<<dim3(DM / 128, TOK / 128), 256, GSMEM>>>(
        p_y, W_out, x, out, DM, DI);
}

// round 11
// speedup vs baseline: 3.8511x; 1.0123x over previous
#include <cuda_runtime.h>
#include <cuda_bf16.h>
#include <math.h>
#include <stdint.h>

// ---------------------------------------------------------------------------
// MambaBlock: B=2, S=1024, D_MODEL=1024, D_INNER=2048, D_STATE=16, D_CONV=4
// Round 11: xproj parallelism 4x (32 k-splits x 16 token-blocks = 512 CTAs).
// ---------------------------------------------------------------------------

#define TOK 2048
#define DM  1024
#define DI  2048
#define DS  16
#define NXP 33
#define SEQL 1024
#define NCHUNK 16
#define CLEN 64
#define KSPLIT 32
#define KSEG (DI / KSPLIT)   // 64

__device__ float g_xn[TOK * DM];
__device__ float g_xz[TOK * 2 * DI];
__device__ float g_xconv_t[TOK * DI];      // [b][ch][t]
__device__ float g_ssm[TOK * NXP];
__device__ float g_dt_t[TOK * DI];         // [b][ch][t]
__device__ float g_y[TOK * DI];
__device__ float g_yt[TOK * DI];           // [b][ch][t]
__device__ float g_xp[KSPLIT * NXP * TOK];

// ------------------------------ helpers ------------------------------------
__device__ __forceinline__ uint32_t smem_u32(const void* p) {
    uint32_t a;
    asm("{ .reg .u64 t; cvta.to.shared.u64 t, %1; cvt.u32.u64 %0, t; }" : "=r"(a) : "l"(p));
    return a;
}
__device__ __forceinline__ void cp_async16(uint32_t dst, const void* src) {
    asm volatile("cp.async.cg.shared.global [%0], [%1], 16;" :: "r"(dst), "l"(src));
}
__device__ __forceinline__ void cp_commit() {
    asm volatile("cp.async.commit_group;");
}
__device__ __forceinline__ void mma_tf32(float* d, const uint32_t* a, const uint32_t* b) {
    asm volatile(
        "mma.sync.aligned.m16n8k8.row.col.f32.tf32.tf32.f32 "
        "{%0,%1,%2,%3}, {%4,%5,%6,%7}, {%8,%9}, {%0,%1,%2,%3};"
        : "+f"(d[0]), "+f"(d[1]), "+f"(d[2]), "+f"(d[3])
        : "r"(a[0]), "r"(a[1]), "r"(a[2]), "r"(a[3]), "r"(b[0]), "r"(b[1]));
}
__device__ __forceinline__ float softplus_f(float x) {
    return (x > 15.f) ? x : log1pf(expf(x));
}
__device__ __forceinline__ float silu_f(float x) {
    return x / (1.f + __expf(-x));
}

// ------------------------- mma.sync tf32 GEMM ------------------------------
#define SAq 36
#define SBq 136
#define ATILEF (128 * SAq)
#define BTILEF (32 * SBq)
#define GSMEM (3 * (ATILEF + BTILEF) * 4)

template <bool RES>
__global__ void __launch_bounds__(256, 2) gemm_mma_kernel(
    const float* __restrict__ A, const float* __restrict__ B,
    const float* __restrict__ Rsd, float* __restrict__ C,
    int Nout, int K)
{
    extern __shared__ __align__(16) float smem[];
    float* As = smem;
    float* Bs = smem + 3 * ATILEF;
    const uint32_t as_u = smem_u32(As);
    const uint32_t bs_u = smem_u32(Bs);

    const int tid = threadIdx.x;
    const int wid = tid >> 5;
    const int lane = tid & 31;
    const int wr = wid & 3;
    const int wc = wid >> 2;
    const int g = lane >> 2;
    const int tig = lane & 3;

    const int row0 = blockIdx.y * 128;
    const int col0 = blockIdx.x * 128;
    const int KT = K >> 5;

    const int alr = tid >> 3;
    const int alc = (tid & 7) << 2;
    const int blr = tid >> 5;
    const int blc = (tid & 31) << 2;

    float acc[2][8][4];
    #pragma unroll
    for (int i = 0; i < 2; i++)
        #pragma unroll
        for (int j = 0; j < 8; j++)
            #pragma unroll
            for (int q = 0; q < 4; q++) acc[i][j][q] = 0.f;

    auto load_stage = [&](int i, int s) {
        const int k0 = i << 5;
        #pragma unroll
        for (int p = 0; p < 4; ++p) {
            const int r = p * 32 + alr;
            cp_async16(as_u + (s * ATILEF + r * SAq + alc) * 4,
                       &A[(size_t)(row0 + r) * K + k0 + alc]);
        }
        #pragma unroll
        for (int p = 0; p < 4; ++p) {
            const int kr = p * 8 + blr;
            cp_async16(bs_u + (s * BTILEF + kr * SBq + blc) * 4,
                       &B[(size_t)(k0 + kr) * Nout + col0 + blc]);
        }
    };

    load_stage(0, 0); cp_commit();
    load_stage(1, 1); cp_commit();

    for (int i = 0; i < KT; ++i) {
        asm volatile("cp.async.wait_group 1;" ::: "memory");
        __syncthreads();
        if (i + 2 < KT) load_stage(i + 2, (i + 2) % 3);
        cp_commit();

        const uint32_t* Ab = reinterpret_cast<const uint32_t*>(As + (i % 3) * ATILEF);
        const uint32_t* Bb = reinterpret_cast<const uint32_t*>(Bs + (i % 3) * BTILEF);
        #pragma unroll
        for (int kk = 0; kk < 4; ++kk) {
            const int k = kk << 3;
            uint32_t afr[2][4];
            #pragma unroll
            for (int mt = 0; mt < 2; ++mt) {
                const int rb = wr * 32 + mt * 16;
                afr[mt][0] = Ab[(rb + g) * SAq + k + tig];
                afr[mt][1] = Ab[(rb + g + 8) * SAq + k + tig];
                afr[mt][2] = Ab[(rb + g) * SAq + k + tig + 4];
                afr[mt][3] = Ab[(rb + g + 8) * SAq + k + tig + 4];
            }
            uint32_t bfr[8][2];
            #pragma unroll
            for (int nt = 0; nt < 8; ++nt) {
                const int cb = wc * 64 + nt * 8 + g;
                bfr[nt][0] = Bb[(k + tig) * SBq + cb];
                bfr[nt][1] = Bb[(k + tig + 4) * SBq + cb];
            }
            #pragma unroll
            for (int mt = 0; mt < 2; ++mt)
                #pragma unroll
                for (int nt = 0; nt < 8; ++nt)
                    mma_tf32(acc[mt][nt], afr[mt], bfr[nt]);
        }
    }

    #pragma unroll
    for (int mt = 0; mt < 2; ++mt) {
        const int r0 = row0 + wr * 32 + mt * 16 + g;
        #pragma unroll
        for (int nt = 0; nt < 8; ++nt) {
            const int c = col0 + wc * 64 + nt * 8 + tig * 2;
            float2 v0 = make_float2(acc[mt][nt][0], acc[mt][nt][1]);
            float2 v1 = make_float2(acc[mt][nt][2], acc[mt][nt][3]);
            if (RES) {
                float2 r0v = *reinterpret_cast<const float2*>(&Rsd[(size_t)r0 * Nout + c]);
                float2 r1v = *reinterpret_cast<const float2*>(&Rsd[(size_t)(r0 + 8) * Nout + c]);
                v0.x += r0v.x; v0.y += r0v.y;
                v1.x += r1v.x; v1.y += r1v.y;
            }
            *reinterpret_cast<float2*>(&C[(size_t)r0 * Nout + c]) = v0;
            *reinterpret_cast<float2*>(&C[(size_t)(r0 + 8) * Nout + c]) = v1;
        }
    }
}

// ------------------------------ rmsnorm ------------------------------------
__global__ void __launch_bounds__(256) rmsnorm_kernel(
    const float* __restrict__ x, const float* __restrict__ w, float* __restrict__ xn)
{
    const int token = blockIdx.x;
    const int tid = threadIdx.x;
    const float4* x4 = reinterpret_cast<const float4*>(x + (size_t)token * DM);
    float4 v = x4[tid];
    float s = v.x * v.x + v.y * v.y + v.z * v.z + v.w * v.w;
    __shared__ float red[8];
    #pragma unroll
    for (int o = 16; o; o >>= 1) s += __shfl_xor_sync(0xffffffffu, s, o);
    if ((tid & 31) == 0) red[tid >> 5] = s;
    __syncthreads();
    if (tid < 32) {
        float t = (tid < 8) ? red[tid] : 0.f;
        #pragma unroll
        for (int o = 4; o; o >>= 1) t += __shfl_xor_sync(0xffffffffu, t, o);
        if (tid == 0) red[0] = t;
    }
    __syncthreads();
    const float ms = red[0] * (1.f / (float)DM);
    const float r = rsqrtf(ms + 1.1920928955078125e-07f);
    const float4* w4 = reinterpret_cast<const float4*>(w);
    float4 wv = w4[tid];
    float4 o;
    o.x = v.x * r * wv.x; o.y = v.y * r * wv.y;
    o.z = v.z * r * wv.z; o.w = v.w * r * wv.w;
    reinterpret_cast<float4*>(xn + (size_t)token * DM)[tid] = o;
}

// ------------- causal depthwise conv + silu, transposed output -------------
__global__ void __launch_bounds__(256) conv_silu_t_kernel(
    const float* __restrict__ xz, const float* __restrict__ cw,
    const float* __restrict__ cb, float* __restrict__ xconv_t)
{
    __shared__ float tile[35][33];
    const int ch0 = blockIdx.x * 32;
    const int t0 = blockIdx.y * 32;
    const int b = blockIdx.z;
    const int tx = threadIdx.x, ty = threadIdx.y;

    for (int j = ty; j < 35; j += 8) {
        const int tg = t0 + j - 3;
        tile[j][tx] = (tg >= 0) ? xz[(size_t)(b * SEQL + tg) * (2 * DI) + ch0 + tx] : 0.f;
    }
    __syncthreads();

    #pragma unroll
    for (int q = 0; q < 4; ++q) {
        const int chl = ty + q * 8;
        const int ch = ch0 + chl;
        float acc = cb[ch];
        #pragma unroll
        for (int k = 0; k < 4; ++k)
            acc = fmaf(tile[tx + k][chl], cw[ch * 4 + k], acc);
        xconv_t[((size_t)b * DI + ch) * SEQL + t0 + tx] = silu_f(acc);
    }
}

// ---------------------- xproj partials (32-way k-split) --------------------
// grid (TOK/128, KSPLIT), block 128.  Each thread: one token, KSEG=64 k-iters.
__global__ void __launch_bounds__(128) xproj_part_kernel(
    const float* __restrict__ xconv_t, const float* __restrict__ W,
    float* __restrict__ part)
{
    __shared__ float Wbuf[KSEG][NXP];
    const int tok = blockIdx.x * 128 + threadIdx.x;
    const int b = tok >> 10;
    const int t = tok & (SEQL - 1);
    const int ks = blockIdx.y;
    const int kbase = ks * KSEG;

    for (int i = threadIdx.x; i < KSEG * NXP; i += 128) {
        const int kr = i / NXP, c = i - kr * NXP;
        Wbuf[kr][c] = W[(size_t)(kbase + kr) * NXP + c];
    }
    __syncthreads();

    float acc[NXP];
    #pragma unroll
    for (int c = 0; c < NXP; ++c) acc[c] = 0.f;

    #pragma unroll 4
    for (int kr = 0; kr < KSEG; ++kr) {
        const float xv = xconv_t[((size_t)b * DI + kbase + kr) * SEQL + t];
        #pragma unroll
        for (int c = 0; c < NXP; ++c)
            acc[c] = fmaf(xv, Wbuf[kr][c], acc[c]);
    }
    #pragma unroll
    for (int c = 0; c < NXP; ++c)
        part[((size_t)ks * NXP + c) * TOK + tok] = acc[c];
}

__global__ void __launch_bounds__(256) xproj_reduce_kernel(
    const float* __restrict__ part, float* __restrict__ ssm)
{
    const int idx = blockIdx.x * 256 + threadIdx.x;
    if (idx >= NXP * TOK) return;
    const int c = idx / TOK;
    const int tok = idx - c * TOK;
    float s = 0.f;
    #pragma unroll
    for (int ks = 0; ks < KSPLIT; ++ks)
        s += part[((size_t)ks * NXP + c) * TOK + tok];
    ssm[(size_t)tok * NXP + c] = s;
}

// ------------------------- dt precompute -----------------------------------
__global__ void __launch_bounds__(256) dt_t_kernel(
    const float* __restrict__ ssm, const float* __restrict__ W_dt,
    const float* __restrict__ b_dt, float* __restrict__ dt_t)
{
    __shared__ float sdt[32];
    const int ch0 = blockIdx.x * 64;
    const int t0 = blockIdx.y * 32;
    const int b = blockIdx.z;
    const int tx = threadIdx.x, ty = threadIdx.y;
    if (ty == 0)
        sdt[tx] = ssm[(size_t)(b * SEQL + t0 + tx) * NXP];
    __syncthreads();
    const float dtr = sdt[tx];
    #pragma unroll
    for (int q = 0; q < 8; ++q) {
        const int ch = ch0 + ty + q * 8;
        const float xv = fmaf(dtr, W_dt[ch], b_dt[ch]);
        dt_t[((size_t)b * DI + ch) * SEQL + t0 + tx] = softplus_f(xv);
    }
}

// --------------------------- fused scan ------------------------------------
__global__ void __launch_bounds__(256) scan_fused_kernel(
    const float* __restrict__ ssm, const float* __restrict__ xconv_t,
    const float* __restrict__ dt_t, const float* __restrict__ A_log,
    const float* __restrict__ Dp, float* __restrict__ yt)
{
    __shared__ float sP[NCHUNK][DS];
    __shared__ float shL[NCHUNK][DS];
    __shared__ float sh0[NCHUNK][DS];
    __shared__ float sy[SEQL];

    const int ch = blockIdx.x;
    const int b = blockIdx.y;
    const int lane = threadIdx.x & 31;
    const int warp = threadIdx.x >> 5;
    const int n = lane & 15;
    const int chunk = warp * 2 + (lane >> 4);

    const float An = -expf(A_log[ch * DS + n]);
    const float Dch = Dp[ch];

    const float* srow0 = ssm + (size_t)(b * SEQL + chunk * CLEN) * NXP;
    const float* xc = xconv_t + ((size_t)b * DI + ch) * SEQL + chunk * CLEN;
    const float* dtp = dt_t + ((size_t)b * DI + ch) * SEQL + chunk * CLEN;

    {
        float h = 0.f, P = 1.f;
        const float* sr = srow0;
        #pragma unroll 4
        for (int t = 0; t < CLEN; ++t) {
            const float Bv = sr[1 + n];
            const float dtv = dtp[t];
            const float ab = __expf(dtv * An);
            h = fmaf(ab, h, dtv * xc[t] * Bv);
            P *= ab;
            sr += NXP;
        }
        sP[chunk][n] = P;
        shL[chunk][n] = h;
    }
    __syncthreads();

    if (threadIdx.x < DS) {
        const int nn = threadIdx.x;
        float h = 0.f;
        #pragma unroll
        for (int c = 0; c < NCHUNK; ++c) {
            sh0[c][nn] = h;
            h = fmaf(sP[c][nn], h, shL[c][nn]);
        }
    }
    __syncthreads();

    {
        float h = sh0[chunk][n];
        const float* sr = srow0;
        #pragma unroll 4
        for (int t = 0; t < CLEN; ++t) {
            const float Bv = sr[1 + n];
            const float Cv = sr[1 + DS + n];
            const float xcv = xc[t];
            const float dtv = dtp[t];
            const float ab = __expf(dtv * An);
            h = fmaf(ab, h, dtv * xcv * Bv);
            float p = h * Cv;
            p += __shfl_xor_sync(0xffffffffu, p, 1);
            p += __shfl_xor_sync(0xffffffffu, p, 2);
            p += __shfl_xor_sync(0xffffffffu, p, 4);
            p += __shfl_xor_sync(0xffffffffu, p, 8);
            if (n == 0) sy[chunk * CLEN + t] = fmaf(xcv, Dch, p);
            sr += NXP;
        }
    }
    __syncthreads();

    float* yrow = yt + ((size_t)b * DI + ch) * SEQL;
    for (int i = threadIdx.x; i < SEQL; i += 256)
        yrow[i] = sy[i];
}

// ------------------------- gate + transpose --------------------------------
__global__ void __launch_bounds__(256) gate_kernel(
    const float* __restrict__ yt, const float* __restrict__ xz,
    float* __restrict__ y)
{
    __shared__ float tile[32][33];
    const int ch0 = blockIdx.x * 32;
    const int t0 = blockIdx.y * 32;
    const int b = blockIdx.z;
    const int tx = threadIdx.x, ty = threadIdx.y;
    #pragma unroll
    for (int j = 0; j < 32; j += 8)
        tile[ty + j][tx] = yt[((size_t)b * DI + ch0 + ty + j) * SEQL + t0 + tx];
    __syncthreads();
    #pragma unroll
    for (int j = 0; j < 32; j += 8) {
        const int tok = b * SEQL + t0 + ty + j;
        const float z = xz[(size_t)tok * (2 * DI) + DI + ch0 + tx];
        y[(size_t)tok * DI + ch0 + tx] = tile[tx][ty + j] * silu_f(z);
    }
}

// ---------------------------------------------------------------------------
extern "C" void kernel_launch(void* const* d_in, const int* in_sizes, int n_in,
                              void* d_out, int out_size)
{
    const float* x      = (const float*)d_in[0];
    const float* W_in   = (const float*)d_in[1];
    const float* conv_w = (const float*)d_in[2];
    const float* conv_b = (const float*)d_in[3];
    const float* W_xproj= (const float*)d_in[4];
    const float* W_dt   = (const float*)d_in[5];
    const float* b_dt   = (const float*)d_in[6];
    const float* A_log  = (const float*)d_in[7];
    const float* Dp     = (const float*)d_in[8];
    const float* W_out  = (const float*)d_in[9];
    const float* norm_w = (const float*)d_in[10];
    float* out = (float*)d_out;

    float *p_xn, *p_xz, *p_xct, *p_ssm, *p_dtt, *p_y, *p_yt, *p_xp;
    cudaGetSymbolAddress((void**)&p_xn, g_xn);
    cudaGetSymbolAddress((void**)&p_xz, g_xz);
    cudaGetSymbolAddress((void**)&p_xct, g_xconv_t);
    cudaGetSymbolAddress((void**)&p_ssm, g_ssm);
    cudaGetSymbolAddress((void**)&p_dtt, g_dt_t);
    cudaGetSymbolAddress((void**)&p_y, g_y);
    cudaGetSymbolAddress((void**)&p_yt, g_yt);
    cudaGetSymbolAddress((void**)&p_xp, g_xp);

    static bool attr_done = false;
    if (!attr_done) {
        cudaFuncSetAttribute(gemm_mma_kernel<false>,
                             cudaFuncAttributeMaxDynamicSharedMemorySize, GSMEM);
        cudaFuncSetAttribute(gemm_mma_kernel<true>,
                             cudaFuncAttributeMaxDynamicSharedMemorySize, GSMEM);
        attr_done = true;
    }

    // 1) rmsnorm
    rmsnorm_kernel<<<TOK, 256>>>(x, norm_w, p_xn);

    // 2) xz = xn @ W_in
    gemm_mma_kernel<false><<<dim3((2 * DI) / 128, TOK / 128), 256, GSMEM>>>(
        p_xn, W_in, nullptr, p_xz, 2 * DI, DM);

    // 3) conv + silu -> [b][ch][t]
    conv_silu_t_kernel<<<dim3(DI / 32, SEQL / 32, 2), dim3(32, 8)>>>(
        p_xz, conv_w, conv_b, p_xct);

    // 4) xproj (32-way k-split)
    xproj_part_kernel<<<dim3(TOK / 128, KSPLIT), 128>>>(p_xct, W_xproj, p_xp);
    xproj_reduce_kernel<<<(NXP * TOK + 255) / 256, 256>>>(p_xp, p_ssm);

    // 5) dt precompute
    dt_t_kernel<<<dim3(DI / 64, SEQL / 32, 2), dim3(32, 8)>>>(
        p_ssm, W_dt, b_dt, p_dtt);

    // 6) fused chunked scan
    scan_fused_kernel<<<dim3(DI, 2), 256>>>(
        p_ssm, p_xct, p_dtt, A_log, Dp, p_yt);

    // 7) gate + transpose back
    gate_kernel<<<dim3(DI / 32, SEQL / 32, 2), dim3(32, 8)>>>(p_yt, p_xz, p_y);

    // 8) out = x + y @ W_out
    gemm_mma_kernel<true><<<dim3(DM / 128, TOK / 128), 256, GSMEM>>>(
        p_y, W_out, x, out, DM, DI);
}

// round 13
// speedup vs baseline: 4.4618x; 1.1586x over previous
#include <cuda_runtime.h>
#include <cuda_bf16.h>
#include <math.h>
#include <stdint.h>

// ---------------------------------------------------------------------------
// MambaBlock: B=2, S=1024, D_MODEL=1024, D_INNER=2048, D_STATE=16, D_CONV=4
// Round 12: scan restructured as 3 phases with smem-staged tiles
// (block = one chunk x 16 channels; all inner-loop reads are LDS),
// gate + output transpose fused into phase C (yt buffer + gate kernel gone).
// ---------------------------------------------------------------------------

#define TOK 2048
#define DM  1024
#define DI  2048
#define DS  16
#define NXP 33
#define SEQL 1024
#define NCHUNK 16
#define CLEN 64
#define KSPLIT 32
#define KSEG (DI / KSPLIT)   // 64

__device__ float g_xn[TOK * DM];
__device__ float g_xz[TOK * 2 * DI];
__device__ float g_xconv_t[TOK * DI];      // [b][ch][t]
__device__ float g_ssm[TOK * NXP];
__device__ float g_dt_t[TOK * DI];         // [b][ch][t]
__device__ float g_y[TOK * DI];
__device__ float g_xp[KSPLIT * NXP * TOK];
__device__ float g_P[2 * NCHUNK * DI * DS];
__device__ float g_hL[2 * NCHUNK * DI * DS];
__device__ float g_h0[2 * NCHUNK * DI * DS];

// ------------------------------ helpers ------------------------------------
__device__ __forceinline__ uint32_t smem_u32(const void* p) {
    uint32_t a;
    asm("{ .reg .u64 t; cvta.to.shared.u64 t, %1; cvt.u32.u64 %0, t; }" : "=r"(a) : "l"(p));
    return a;
}
__device__ __forceinline__ void cp_async16(uint32_t dst, const void* src) {
    asm volatile("cp.async.cg.shared.global [%0], [%1], 16;" :: "r"(dst), "l"(src));
}
__device__ __forceinline__ void cp_commit() {
    asm volatile("cp.async.commit_group;");
}
__device__ __forceinline__ void mma_tf32(float* d, const uint32_t* a, const uint32_t* b) {
    asm volatile(
        "mma.sync.aligned.m16n8k8.row.col.f32.tf32.tf32.f32 "
        "{%0,%1,%2,%3}, {%4,%5,%6,%7}, {%8,%9}, {%0,%1,%2,%3};"
        : "+f"(d[0]), "+f"(d[1]), "+f"(d[2]), "+f"(d[3])
        : "r"(a[0]), "r"(a[1]), "r"(a[2]), "r"(a[3]), "r"(b[0]), "r"(b[1]));
}
__device__ __forceinline__ float softplus_f(float x) {
    return (x > 15.f) ? x : log1pf(expf(x));
}
__device__ __forceinline__ float silu_f(float x) {
    return x / (1.f + __expf(-x));
}

// ------------------------- mma.sync tf32 GEMM ------------------------------
#define SAq 36
#define SBq 136
#define ATILEF (128 * SAq)
#define BTILEF (32 * SBq)
#define GSMEM (3 * (ATILEF + BTILEF) * 4)

template <bool RES>
__global__ void __launch_bounds__(256, 2) gemm_mma_kernel(
    const float* __restrict__ A, const float* __restrict__ B,
    const float* __restrict__ Rsd, float* __restrict__ C,
    int Nout, int K)
{
    extern __shared__ __align__(16) float smem[];
    float* As = smem;
    float* Bs = smem + 3 * ATILEF;
    const uint32_t as_u = smem_u32(As);
    const uint32_t bs_u = smem_u32(Bs);

    const int tid = threadIdx.x;
    const int wid = tid >> 5;
    const int lane = tid & 31;
    const int wr = wid & 3;
    const int wc = wid >> 2;
    const int g = lane >> 2;
    const int tig = lane & 3;

    const int row0 = blockIdx.y * 128;
    const int col0 = blockIdx.x * 128;
    const int KT = K >> 5;

    const int alr = tid >> 3;
    const int alc = (tid & 7) << 2;
    const int blr = tid >> 5;
    const int blc = (tid & 31) << 2;

    float acc[2][8][4];
    #pragma unroll
    for (int i = 0; i < 2; i++)
        #pragma unroll
        for (int j = 0; j < 8; j++)
            #pragma unroll
            for (int q = 0; q < 4; q++) acc[i][j][q] = 0.f;

    auto load_stage = [&](int i, int s) {
        const int k0 = i << 5;
        #pragma unroll
        for (int p = 0; p < 4; ++p) {
            const int r = p * 32 + alr;
            cp_async16(as_u + (s * ATILEF + r * SAq + alc) * 4,
                       &A[(size_t)(row0 + r) * K + k0 + alc]);
        }
        #pragma unroll
        for (int p = 0; p < 4; ++p) {
            const int kr = p * 8 + blr;
            cp_async16(bs_u + (s * BTILEF + kr * SBq + blc) * 4,
                       &B[(size_t)(k0 + kr) * Nout + col0 + blc]);
        }
    };

    load_stage(0, 0); cp_commit();
    load_stage(1, 1); cp_commit();

    for (int i = 0; i < KT; ++i) {
        asm volatile("cp.async.wait_group 1;" ::: "memory");
        __syncthreads();
        if (i + 2 < KT) load_stage(i + 2, (i + 2) % 3);
        cp_commit();

        const uint32_t* Ab = reinterpret_cast<const uint32_t*>(As + (i % 3) * ATILEF);
        const uint32_t* Bb = reinterpret_cast<const uint32_t*>(Bs + (i % 3) * BTILEF);
        #pragma unroll
        for (int kk = 0; kk < 4; ++kk) {
            const int k = kk << 3;
            uint32_t afr[2][4];
            #pragma unroll
            for (int mt = 0; mt < 2; ++mt) {
                const int rb = wr * 32 + mt * 16;
                afr[mt][0] = Ab[(rb + g) * SAq + k + tig];
                afr[mt][1] = Ab[(rb + g + 8) * SAq + k + tig];
                afr[mt][2] = Ab[(rb + g) * SAq + k + tig + 4];
                afr[mt][3] = Ab[(rb + g + 8) * SAq + k + tig + 4];
            }
            uint32_t bfr[8][2];
            #pragma unroll
            for (int nt = 0; nt < 8; ++nt) {
                const int cb = wc * 64 + nt * 8 + g;
                bfr[nt][0] = Bb[(k + tig) * SBq + cb];
                bfr[nt][1] = Bb[(k + tig + 4) * SBq + cb];
            }
            #pragma unroll
            for (int mt = 0; mt < 2; ++mt)
                #pragma unroll
                for (int nt = 0; nt < 8; ++nt)
                    mma_tf32(acc[mt][nt], afr[mt], bfr[nt]);
        }
    }

    #pragma unroll
    for (int mt = 0; mt < 2; ++mt) {
        const int r0 = row0 + wr * 32 + mt * 16 + g;
        #pragma unroll
        for (int nt = 0; nt < 8; ++nt) {
            const int c = col0 + wc * 64 + nt * 8 + tig * 2;
            float2 v0 = make_float2(acc[mt][nt][0], acc[mt][nt][1]);
            float2 v1 = make_float2(acc[mt][nt][2], acc[mt][nt][3]);
            if (RES) {
                float2 r0v = *reinterpret_cast<const float2*>(&Rsd[(size_t)r0 * Nout + c]);
                float2 r1v = *reinterpret_cast<const float2*>(&Rsd[(size_t)(r0 + 8) * Nout + c]);
                v0.x += r0v.x; v0.y += r0v.y;
                v1.x += r1v.x; v1.y += r1v.y;
            }
            *reinterpret_cast<float2*>(&C[(size_t)r0 * Nout + c]) = v0;
            *reinterpret_cast<float2*>(&C[(size_t)(r0 + 8) * Nout + c]) = v1;
        }
    }
}

// ------------------------------ rmsnorm ------------------------------------
__global__ void __launch_bounds__(256) rmsnorm_kernel(
    const float* __restrict__ x, const float* __restrict__ w, float* __restrict__ xn)
{
    const int token = blockIdx.x;
    const int tid = threadIdx.x;
    const float4* x4 = reinterpret_cast<const float4*>(x + (size_t)token * DM);
    float4 v = x4[tid];
    float s = v.x * v.x + v.y * v.y + v.z * v.z + v.w * v.w;
    __shared__ float red[8];
    #pragma unroll
    for (int o = 16; o; o >>= 1) s += __shfl_xor_sync(0xffffffffu, s, o);
    if ((tid & 31) == 0) red[tid >> 5] = s;
    __syncthreads();
    if (tid < 32) {
        float t = (tid < 8) ? red[tid] : 0.f;
        #pragma unroll
        for (int o = 4; o; o >>= 1) t += __shfl_xor_sync(0xffffffffu, t, o);
        if (tid == 0) red[0] = t;
    }
    __syncthreads();
    const float ms = red[0] * (1.f / (float)DM);
    const float r = rsqrtf(ms + 1.1920928955078125e-07f);
    const float4* w4 = reinterpret_cast<const float4*>(w);
    float4 wv = w4[tid];
    float4 o;
    o.x = v.x * r * wv.x; o.y = v.y * r * wv.y;
    o.z = v.z * r * wv.z; o.w = v.w * r * wv.w;
    reinterpret_cast<float4*>(xn + (size_t)token * DM)[tid] = o;
}

// ------------- causal depthwise conv + silu, transposed output -------------
__global__ void __launch_bounds__(256) conv_silu_t_kernel(
    const float* __restrict__ xz, const float* __restrict__ cw,
    const float* __restrict__ cb, float* __restrict__ xconv_t)
{
    __shared__ float tile[35][33];
    const int ch0 = blockIdx.x * 32;
    const int t0 = blockIdx.y * 32;
    const int b = blockIdx.z;
    const int tx = threadIdx.x, ty = threadIdx.y;

    for (int j = ty; j < 35; j += 8) {
        const int tg = t0 + j - 3;
        tile[j][tx] = (tg >= 0) ? xz[(size_t)(b * SEQL + tg) * (2 * DI) + ch0 + tx] : 0.f;
    }
    __syncthreads();

    #pragma unroll
    for (int q = 0; q < 4; ++q) {
        const int chl = ty + q * 8;
        const int ch = ch0 + chl;
        float acc = cb[ch];
        #pragma unroll
        for (int k = 0; k < 4; ++k)
            acc = fmaf(tile[tx + k][chl], cw[ch * 4 + k], acc);
        xconv_t[((size_t)b * DI + ch) * SEQL + t0 + tx] = silu_f(acc);
    }
}

// ---------------------- xproj partials (32-way k-split) --------------------
__global__ void __launch_bounds__(128) xproj_part_kernel(
    const float* __restrict__ xconv_t, const float* __restrict__ W,
    float* __restrict__ part)
{
    __shared__ float Wbuf[KSEG][NXP];
    const int tok = blockIdx.x * 128 + threadIdx.x;
    const int b = tok >> 10;
    const int t = tok & (SEQL - 1);
    const int ks = blockIdx.y;
    const int kbase = ks * KSEG;

    for (int i = threadIdx.x; i < KSEG * NXP; i += 128) {
        const int kr = i / NXP, c = i - kr * NXP;
        Wbuf[kr][c] = W[(size_t)(kbase + kr) * NXP + c];
    }
    __syncthreads();

    float acc[NXP];
    #pragma unroll
    for (int c = 0; c < NXP; ++c) acc[c] = 0.f;

    #pragma unroll 4
    for (int kr = 0; kr < KSEG; ++kr) {
        const float xv = xconv_t[((size_t)b * DI + kbase + kr) * SEQL + t];
        #pragma unroll
        for (int c = 0; c < NXP; ++c)
            acc[c] = fmaf(xv, Wbuf[kr][c], acc[c]);
    }
    #pragma unroll
    for (int c = 0; c < NXP; ++c)
        part[((size_t)ks * NXP + c) * TOK + tok] = acc[c];
}

__global__ void __launch_bounds__(256) xproj_reduce_kernel(
    const float* __restrict__ part, float* __restrict__ ssm)
{
    const int idx = blockIdx.x * 256 + threadIdx.x;
    if (idx >= NXP * TOK) return;
    const int c = idx / TOK;
    const int tok = idx - c * TOK;
    float s = 0.f;
    #pragma unroll
    for (int ks = 0; ks < KSPLIT; ++ks)
        s += part[((size_t)ks * NXP + c) * TOK + tok];
    ssm[(size_t)tok * NXP + c] = s;
}

// ------------------------- dt precompute -----------------------------------
__global__ void __launch_bounds__(256) dt_t_kernel(
    const float* __restrict__ ssm, const float* __restrict__ W_dt,
    const float* __restrict__ b_dt, float* __restrict__ dt_t)
{
    __shared__ float sdt[32];
    const int ch0 = blockIdx.x * 64;
    const int t0 = blockIdx.y * 32;
    const int b = blockIdx.z;
    const int tx = threadIdx.x, ty = threadIdx.y;
    if (ty == 0)
        sdt[tx] = ssm[(size_t)(b * SEQL + t0 + tx) * NXP];
    __syncthreads();
    const float dtr = sdt[tx];
    #pragma unroll
    for (int q = 0; q < 8; ++q) {
        const int ch = ch0 + ty + q * 8;
        const float xv = fmaf(dtr, W_dt[ch], b_dt[ch]);
        dt_t[((size_t)b * DI + ch) * SEQL + t0 + tx] = softplus_f(xv);
    }
}

// --------------------------- scan phase A ----------------------------------
// Block 256 = 16 ch x 16 n, one chunk.  Grid (DI/16, NCHUNK, B).
// All inner-loop reads staged in smem (coalesced global loads once).
__global__ void __launch_bounds__(256) scan_a_kernel(
    const float* __restrict__ ssm, const float* __restrict__ xconv_t,
    const float* __restrict__ dt_t, const float* __restrict__ A_log,
    float* __restrict__ Pout, float* __restrict__ hLout)
{
    __shared__ float sB[CLEN][DS];
    __shared__ float sxc[16][CLEN];
    __shared__ float sdt[16][CLEN];

    const int ch0 = blockIdx.x * 16;
    const int chunk = blockIdx.y;
    const int b = blockIdx.z;
    const int tid = threadIdx.x;
    const int chl = tid >> 4;
    const int n = tid & 15;
    const int ch = ch0 + chl;
    const int t0 = chunk * CLEN;

    // stage B columns: rows of 16 consecutive floats
    for (int i = tid; i < CLEN * DS; i += 256) {
        const int t = i >> 4, nn = i & 15;
        sB[t][nn] = ssm[(size_t)(b * SEQL + t0 + t) * NXP + 1 + nn];
    }
    // stage xc, dt: contiguous 256B rows
    for (int i = tid; i < 16 * CLEN; i += 256) {
        const int r = i >> 6, t = i & 63;
        sxc[r][t] = xconv_t[((size_t)b * DI + ch0 + r) * SEQL + t0 + t];
        sdt[r][t] = dt_t[((size_t)b * DI + ch0 + r) * SEQL + t0 + t];
    }
    __syncthreads();

    const float An = -expf(A_log[ch * DS + n]);
    float h = 0.f, P = 1.f;
    #pragma unroll 4
    for (int t = 0; t < CLEN; ++t) {
        const float dtv = sdt[chl][t];
        const float ab = __expf(dtv * An);
        h = fmaf(ab, h, dtv * sxc[chl][t] * sB[t][n]);
        P *= ab;
    }
    const size_t idx = (((size_t)b * NCHUNK + chunk) * DI + ch) * DS + n;
    Pout[idx] = P;
    hLout[idx] = h;
}

// --------------------------- scan phase B ----------------------------------
__global__ void __launch_bounds__(256) scan_b_kernel(
    const float* __restrict__ P, const float* __restrict__ hL,
    float* __restrict__ h0)
{
    const int gid = blockIdx.x * 256 + threadIdx.x;
    const int b = gid / (DI * DS);
    const int r = gid - b * (DI * DS);
    float h = 0.f;
    #pragma unroll
    for (int c = 0; c < NCHUNK; ++c) {
        const size_t idx = ((size_t)(b * NCHUNK + c)) * (DI * DS) + r;
        h0[idx] = h;
        h = fmaf(P[idx], h, hL[idx]);
    }
}

// --------------------------- scan phase C + gate ---------------------------
// Same blocking as phase A; emits gated y in [tok][ch] layout directly.
__global__ void __launch_bounds__(256) scan_c_kernel(
    const float* __restrict__ ssm, const float* __restrict__ xconv_t,
    const float* __restrict__ dt_t, const float* __restrict__ A_log,
    const float* __restrict__ Dp, const float* __restrict__ h0,
    const float* __restrict__ xz, float* __restrict__ y)
{
    __shared__ float sB[CLEN][DS];
    __shared__ float sC[CLEN][DS];
    __shared__ float sxc[16][CLEN];
    __shared__ float sdt[16][CLEN];
    __shared__ float sy[16][CLEN + 1];

    const int ch0 = blockIdx.x * 16;
    const int chunk = blockIdx.y;
    const int b = blockIdx.z;
    const int tid = threadIdx.x;
    const int chl = tid >> 4;
    const int n = tid & 15;
    const int ch = ch0 + chl;
    const int t0 = chunk * CLEN;

    for (int i = tid; i < CLEN * DS; i += 256) {
        const int t = i >> 4, nn = i & 15;
        const float* row = &ssm[(size_t)(b * SEQL + t0 + t) * NXP];
        sB[t][nn] = row[1 + nn];
        sC[t][nn] = row[1 + DS + nn];
    }
    for (int i = tid; i < 16 * CLEN; i += 256) {
        const int r = i >> 6, t = i & 63;
        sxc[r][t] = xconv_t[((size_t)b * DI + ch0 + r) * SEQL + t0 + t];
        sdt[r][t] = dt_t[((size_t)b * DI + ch0 + r) * SEQL + t0 + t];
    }
    __syncthreads();

    const float An = -expf(A_log[ch * DS + n]);
    const float Dch = Dp[ch];
    float h = h0[(((size_t)b * NCHUNK + chunk) * DI + ch) * DS + n];

    #pragma unroll 4
    for (int t = 0; t < CLEN; ++t) {
        const float dtv = sdt[chl][t];
        const float xcv = sxc[chl][t];
        const float ab = __expf(dtv * An);
        h = fmaf(ab, h, dtv * xcv * sB[t][n]);
        float p = h * sC[t][n];
        p += __shfl_xor_sync(0xffffffffu, p, 1);
        p += __shfl_xor_sync(0xffffffffu, p, 2);
        p += __shfl_xor_sync(0xffffffffu, p, 4);
        p += __shfl_xor_sync(0xffffffffu, p, 8);
        if (n == 0) sy[chl][t] = fmaf(xcv, Dch, p);
    }
    __syncthreads();

    // gate + write y[tok][ch0..ch0+15] (rows of 64B)
    for (int i = tid; i < CLEN * 16; i += 256) {
        const int t = i >> 4, c = i & 15;
        const int tok = b * SEQL + t0 + t;
        const float z = xz[(size_t)tok * (2 * DI) + DI + ch0 + c];
        y[(size_t)tok * DI + ch0 + c] = sy[c][t] * silu_f(z);
    }
}

// ---------------------------------------------------------------------------
extern "C" void kernel_launch(void* const* d_in, const int* in_sizes, int n_in,
                              void* d_out, int out_size)
{
    const float* x      = (const float*)d_in[0];
    const float* W_in   = (const float*)d_in[1];
    const float* conv_w = (const float*)d_in[2];
    const float* conv_b = (const float*)d_in[3];
    const float* W_xproj= (const float*)d_in[4];
    const float* W_dt   = (const float*)d_in[5];
    const float* b_dt   = (const float*)d_in[6];
    const float* A_log  = (const float*)d_in[7];
    const float* Dp     = (const float*)d_in[8];
    const float* W_out  = (const float*)d_in[9];
    const float* norm_w = (const float*)d_in[10];
    float* out = (float*)d_out;

    float *p_xn, *p_xz, *p_xct, *p_ssm, *p_dtt, *p_y, *p_xp, *p_P, *p_hL, *p_h0;
    cudaGetSymbolAddress((void**)&p_xn, g_xn);
    cudaGetSymbolAddress((void**)&p_xz, g_xz);
    cudaGetSymbolAddress((void**)&p_xct, g_xconv_t);
    cudaGetSymbolAddress((void**)&p_ssm, g_ssm);
    cudaGetSymbolAddress((void**)&p_dtt, g_dt_t);
    cudaGetSymbolAddress((void**)&p_y, g_y);
    cudaGetSymbolAddress((void**)&p_xp, g_xp);
    cudaGetSymbolAddress((void**)&p_P, g_P);
    cudaGetSymbolAddress((void**)&p_hL, g_hL);
    cudaGetSymbolAddress((void**)&p_h0, g_h0);

    static bool attr_done = false;
    if (!attr_done) {
        cudaFuncSetAttribute(gemm_mma_kernel<false>,
                             cudaFuncAttributeMaxDynamicSharedMemorySize, GSMEM);
        cudaFuncSetAttribute(gemm_mma_kernel<true>,
                             cudaFuncAttributeMaxDynamicSharedMemorySize, GSMEM);
        attr_done = true;
    }

    // 1) rmsnorm
    rmsnorm_kernel<<<TOK, 256>>>(x, norm_w, p_xn);

    // 2) xz = xn @ W_in
    gemm_mma_kernel<false><<<dim3((2 * DI) / 128, TOK / 128), 256, GSMEM>>>(
        p_xn, W_in, nullptr, p_xz, 2 * DI, DM);

    // 3) conv + silu -> [b][ch][t]
    conv_silu_t_kernel<<<dim3(DI / 32, SEQL / 32, 2), dim3(32, 8)>>>(
        p_xz, conv_w, conv_b, p_xct);

    // 4) xproj
    xproj_part_kernel<<<dim3(TOK / 128, KSPLIT), 128>>>(p_xct, W_xproj, p_xp);
    xproj_reduce_kernel<<<(NXP * TOK + 255) / 256, 256>>>(p_xp, p_ssm);

    // 5) dt precompute
    dt_t_kernel<<<dim3(DI / 64, SEQL / 32, 2), dim3(32, 8)>>>(
        p_ssm, W_dt, b_dt, p_dtt);

    // 6) 3-phase scan (staged), gate fused into phase C
    scan_a_kernel<<<dim3(DI / 16, NCHUNK, 2), 256>>>(
        p_ssm, p_xct, p_dtt, A_log, p_P, p_hL);
    scan_b_kernel<<<(2 * DI * DS) / 256, 256>>>(p_P, p_hL, p_h0);
    scan_c_kernel<<<dim3(DI / 16, NCHUNK, 2), 256>>>(
        p_ssm, p_xct, p_dtt, A_log, Dp, p_h0, p_xz, p_y);

    // 7) out = x + y @ W_out
    gemm_mma_kernel<true><<<dim3(DM / 128, TOK / 128), 256, GSMEM>>>(
        p_y, W_out, x, out, DM, DI);
}

// round 15
// speedup vs baseline: 5.2926x; 1.1862x over previous
#include <cuda_runtime.h>
#include <cuda_bf16.h>
#include <math.h>
#include <stdint.h>

// ---------------------------------------------------------------------------
// MambaBlock: B=2, S=1024, D_MODEL=1024, D_INNER=2048, D_STATE=16, D_CONV=4
// Round 14: GEMMs on bf16 m16n8k16 (2x tensor rate vs tf32, half the operand
// traffic). Weights cvt+transposed to bf16 [N,K] per launch; xn / y staged
// in bf16. Accumulate + residual fp32. Non-GEMM pipeline unchanged.
// ---------------------------------------------------------------------------

#define TOK 2048
#define DM  1024
#define DI  2048
#define DS  16
#define NXP 33
#define SEQL 1024
#define NCHUNK 16
#define CLEN 64
#define KSPLIT 32
#define KSEG (DI / KSPLIT)   // 64

__device__ __nv_bfloat16 g_xn[TOK * DM];
__device__ __nv_bfloat16 g_y[TOK * DI];
__device__ __nv_bfloat16 g_WinT[2 * DI * DM];   // [4096,1024] bf16
__device__ __nv_bfloat16 g_WoutT[DM * DI];      // [1024,2048] bf16
__device__ float g_xz[TOK * 2 * DI];
__device__ float g_xconv_t[TOK * DI];      // [b][ch][t]
__device__ float g_ssm[TOK * NXP];
__device__ float g_dt_t[TOK * DI];         // [b][ch][t]
__device__ float g_xp[KSPLIT * NXP * TOK];
__device__ float g_P[2 * NCHUNK * DI * DS];
__device__ float g_hL[2 * NCHUNK * DI * DS];
__device__ float g_h0[2 * NCHUNK * DI * DS];

// ------------------------------ helpers ------------------------------------
__device__ __forceinline__ uint32_t smem_u32(const void* p) {
    uint32_t a;
    asm("{ .reg .u64 t; cvta.to.shared.u64 t, %1; cvt.u32.u64 %0, t; }" : "=r"(a) : "l"(p));
    return a;
}
__device__ __forceinline__ void cp_async16(uint32_t dst, const void* src) {
    asm volatile("cp.async.cg.shared.global [%0], [%1], 16;" :: "r"(dst), "l"(src));
}
__device__ __forceinline__ void cp_commit() {
    asm volatile("cp.async.commit_group;");
}
__device__ __forceinline__ void mma_bf16(float* d, const uint32_t* a, const uint32_t* b) {
    asm volatile(
        "mma.sync.aligned.m16n8k16.row.col.f32.bf16.bf16.f32 "
        "{%0,%1,%2,%3}, {%4,%5,%6,%7}, {%8,%9}, {%0,%1,%2,%3};"
        : "+f"(d[0]), "+f"(d[1]), "+f"(d[2]), "+f"(d[3])
        : "r"(a[0]), "r"(a[1]), "r"(a[2]), "r"(a[3]), "r"(b[0]), "r"(b[1]));
}
__device__ __forceinline__ float softplus_f(float x) {
    return (x > 15.f) ? x : log1pf(expf(x));
}
__device__ __forceinline__ float silu_f(float x) {
    return x / (1.f + __expf(-x));
}

// ------------------------- mma.sync bf16 GEMM ------------------------------
// C[M,N] = A[M,K] @ Bt[N,K]^T (+ Rsd fp32).  A, Bt bf16.  3-stage cp.async.
#define SAb 40                      // bf16 row stride (80 B)
#define TILEB (128 * SAb)           // bf16 elems per tile
#define GSMEMB (3 * 2 * TILEB * 2)  // bytes

template <bool RES>
__global__ void __launch_bounds__(256, 2) gemm_bf16_kernel(
    const __nv_bfloat16* __restrict__ A, const __nv_bfloat16* __restrict__ Bt,
    const float* __restrict__ Rsd, float* __restrict__ C,
    int Nout, int K)
{
    extern __shared__ __align__(16) __nv_bfloat16 smemb[];
    __nv_bfloat16* As = smemb;
    __nv_bfloat16* Bs = smemb + 3 * TILEB;
    const uint32_t as_u = smem_u32(As);
    const uint32_t bs_u = smem_u32(Bs);

    const int tid = threadIdx.x;
    const int wid = tid >> 5;
    const int lane = tid & 31;
    const int wr = wid & 3;
    const int wc = wid >> 2;
    const int g = lane >> 2;
    const int tig = lane & 3;

    const int row0 = blockIdx.y * 128;
    const int col0 = blockIdx.x * 128;
    const int KT = K >> 5;

    float acc[2][8][4];
    #pragma unroll
    for (int i = 0; i < 2; i++)
        #pragma unroll
        for (int j = 0; j < 8; j++)
            #pragma unroll
            for (int q = 0; q < 4; q++) acc[i][j][q] = 0.f;

    auto load_stage = [&](int i, int st) {
        const int k0 = i << 5;
        #pragma unroll
        for (int it = 0; it < 2; ++it) {
            const int s = it * 256 + tid;
            const int r = s >> 2;
            const int c = (s & 3) << 3;       // bf16 col, 8 per 16B
            cp_async16(as_u + (st * TILEB + r * SAb + c) * 2,
                       &A[(size_t)(row0 + r) * K + k0 + c]);
            cp_async16(bs_u + (st * TILEB + r * SAb + c) * 2,
                       &Bt[(size_t)(col0 + r) * K + k0 + c]);
        }
    };

    load_stage(0, 0); cp_commit();
    load_stage(1, 1); cp_commit();

    for (int i = 0; i < KT; ++i) {
        asm volatile("cp.async.wait_group 1;" ::: "memory");
        __syncthreads();
        if (i + 2 < KT) load_stage(i + 2, (i + 2) % 3);
        cp_commit();

        const uint32_t* Ab = reinterpret_cast<const uint32_t*>(As + (i % 3) * TILEB);
        const uint32_t* Bb = reinterpret_cast<const uint32_t*>(Bs + (i % 3) * TILEB);
        #pragma unroll
        for (int ks = 0; ks < 2; ++ks) {
            const int kb2 = (ks * 16) >> 1;          // u32 offset of k-base
            uint32_t afr[2][4];
            #pragma unroll
            for (int mt = 0; mt < 2; ++mt) {
                const int rb = wr * 32 + mt * 16;
                const int o0 = ((rb + g) * SAb) / 2 + kb2 + tig;
                const int o1 = ((rb + g + 8) * SAb) / 2 + kb2 + tig;
                afr[mt][0] = Ab[o0];
                afr[mt][1] = Ab[o1];
                afr[mt][2] = Ab[o0 + 4];
                afr[mt][3] = Ab[o1 + 4];
            }
            uint32_t bfr[8][2];
            #pragma unroll
            for (int nt = 0; nt < 8; ++nt) {
                const int cb = wc * 64 + nt * 8 + g;
                const int ob = (cb * SAb) / 2 + kb2 + tig;
                bfr[nt][0] = Bb[ob];
                bfr[nt][1] = Bb[ob + 4];
            }
            #pragma unroll
            for (int mt = 0; mt < 2; ++mt)
                #pragma unroll
                for (int nt = 0; nt < 8; ++nt)
                    mma_bf16(acc[mt][nt], afr[mt], bfr[nt]);
        }
    }

    #pragma unroll
    for (int mt = 0; mt < 2; ++mt) {
        const int r0 = row0 + wr * 32 + mt * 16 + g;
        #pragma unroll
        for (int nt = 0; nt < 8; ++nt) {
            const int c = col0 + wc * 64 + nt * 8 + tig * 2;
            float2 v0 = make_float2(acc[mt][nt][0], acc[mt][nt][1]);
            float2 v1 = make_float2(acc[mt][nt][2], acc[mt][nt][3]);
            if (RES) {
                float2 r0v = *reinterpret_cast<const float2*>(&Rsd[(size_t)r0 * Nout + c]);
                float2 r1v = *reinterpret_cast<const float2*>(&Rsd[(size_t)(r0 + 8) * Nout + c]);
                v0.x += r0v.x; v0.y += r0v.y;
                v1.x += r1v.x; v1.y += r1v.y;
            }
            *reinterpret_cast<float2*>(&C[(size_t)r0 * Nout + c]) = v0;
            *reinterpret_cast<float2*>(&C[(size_t)(r0 + 8) * Nout + c]) = v1;
        }
    }
}

// ---------------- weight convert + transpose (fp32[R,C] -> bf16[C,R]) ------
__global__ void __launch_bounds__(256) cvtT_kernel(
    const float* __restrict__ in, __nv_bfloat16* __restrict__ out, int R, int Ccols)
{
    __shared__ float tile[32][33];
    const int c0 = blockIdx.x * 32, r0 = blockIdx.y * 32;
    const int x = threadIdx.x, y = threadIdx.y;
    #pragma unroll
    for (int j = 0; j < 32; j += 8)
        tile[y + j][x] = in[(size_t)(r0 + y + j) * Ccols + c0 + x];
    __syncthreads();
    #pragma unroll
    for (int j = 0; j < 32; j += 8)
        out[(size_t)(c0 + y + j) * R + r0 + x] = __float2bfloat16(tile[x][y + j]);
}

// ------------------------------ rmsnorm (bf16 out) -------------------------
__global__ void __launch_bounds__(256) rmsnorm_kernel(
    const float* __restrict__ x, const float* __restrict__ w,
    __nv_bfloat16* __restrict__ xn)
{
    const int token = blockIdx.x;
    const int tid = threadIdx.x;
    const float4* x4 = reinterpret_cast<const float4*>(x + (size_t)token * DM);
    float4 v = x4[tid];
    float s = v.x * v.x + v.y * v.y + v.z * v.z + v.w * v.w;
    __shared__ float red[8];
    #pragma unroll
    for (int o = 16; o; o >>= 1) s += __shfl_xor_sync(0xffffffffu, s, o);
    if ((tid & 31) == 0) red[tid >> 5] = s;
    __syncthreads();
    if (tid < 32) {
        float t = (tid < 8) ? red[tid] : 0.f;
        #pragma unroll
        for (int o = 4; o; o >>= 1) t += __shfl_xor_sync(0xffffffffu, t, o);
        if (tid == 0) red[0] = t;
    }
    __syncthreads();
    const float ms = red[0] * (1.f / (float)DM);
    const float r = rsqrtf(ms + 1.1920928955078125e-07f);
    const float4* w4 = reinterpret_cast<const float4*>(w);
    float4 wv = w4[tid];
    __nv_bfloat162* o2 = reinterpret_cast<__nv_bfloat162*>(xn + (size_t)token * DM) + tid * 2;
    o2[0] = __floats2bfloat162_rn(v.x * r * wv.x, v.y * r * wv.y);
    o2[1] = __floats2bfloat162_rn(v.z * r * wv.z, v.w * r * wv.w);
}

// ------------- causal depthwise conv + silu, transposed output -------------
__global__ void __launch_bounds__(256) conv_silu_t_kernel(
    const float* __restrict__ xz, const float* __restrict__ cw,
    const float* __restrict__ cb, float* __restrict__ xconv_t)
{
    __shared__ float tile[35][33];
    const int ch0 = blockIdx.x * 32;
    const int t0 = blockIdx.y * 32;
    const int b = blockIdx.z;
    const int tx = threadIdx.x, ty = threadIdx.y;

    for (int j = ty; j < 35; j += 8) {
        const int tg = t0 + j - 3;
        tile[j][tx] = (tg >= 0) ? xz[(size_t)(b * SEQL + tg) * (2 * DI) + ch0 + tx] : 0.f;
    }
    __syncthreads();

    #pragma unroll
    for (int q = 0; q < 4; ++q) {
        const int chl = ty + q * 8;
        const int ch = ch0 + chl;
        float acc = cb[ch];
        #pragma unroll
        for (int k = 0; k < 4; ++k)
            acc = fmaf(tile[tx + k][chl], cw[ch * 4 + k], acc);
        xconv_t[((size_t)b * DI + ch) * SEQL + t0 + tx] = silu_f(acc);
    }
}

// ---------------------- xproj partials (32-way k-split) --------------------
__global__ void __launch_bounds__(128) xproj_part_kernel(
    const float* __restrict__ xconv_t, const float* __restrict__ W,
    float* __restrict__ part)
{
    __shared__ float Wbuf[KSEG][NXP];
    const int tok = blockIdx.x * 128 + threadIdx.x;
    const int b = tok >> 10;
    const int t = tok & (SEQL - 1);
    const int ks = blockIdx.y;
    const int kbase = ks * KSEG;

    for (int i = threadIdx.x; i < KSEG * NXP; i += 128) {
        const int kr = i / NXP, c = i - kr * NXP;
        Wbuf[kr][c] = W[(size_t)(kbase + kr) * NXP + c];
    }
    __syncthreads();

    float acc[NXP];
    #pragma unroll
    for (int c = 0; c < NXP; ++c) acc[c] = 0.f;

    #pragma unroll 4
    for (int kr = 0; kr < KSEG; ++kr) {
        const float xv = xconv_t[((size_t)b * DI + kbase + kr) * SEQL + t];
        #pragma unroll
        for (int c = 0; c < NXP; ++c)
            acc[c] = fmaf(xv, Wbuf[kr][c], acc[c]);
    }
    #pragma unroll
    for (int c = 0; c < NXP; ++c)
        part[((size_t)ks * NXP + c) * TOK + tok] = acc[c];
}

__global__ void __launch_bounds__(256) xproj_reduce_kernel(
    const float* __restrict__ part, float* __restrict__ ssm)
{
    const int idx = blockIdx.x * 256 + threadIdx.x;
    if (idx >= NXP * TOK) return;
    const int c = idx / TOK;
    const int tok = idx - c * TOK;
    float s = 0.f;
    #pragma unroll
    for (int ks = 0; ks < KSPLIT; ++ks)
        s += part[((size_t)ks * NXP + c) * TOK + tok];
    ssm[(size_t)tok * NXP + c] = s;
}

// ------------------------- dt precompute -----------------------------------
__global__ void __launch_bounds__(256) dt_t_kernel(
    const float* __restrict__ ssm, const float* __restrict__ W_dt,
    const float* __restrict__ b_dt, float* __restrict__ dt_t)
{
    __shared__ float sdt[32];
    const int ch0 = blockIdx.x * 64;
    const int t0 = blockIdx.y * 32;
    const int b = blockIdx.z;
    const int tx = threadIdx.x, ty = threadIdx.y;
    if (ty == 0)
        sdt[tx] = ssm[(size_t)(b * SEQL + t0 + tx) * NXP];
    __syncthreads();
    const float dtr = sdt[tx];
    #pragma unroll
    for (int q = 0; q < 8; ++q) {
        const int ch = ch0 + ty + q * 8;
        const float xv = fmaf(dtr, W_dt[ch], b_dt[ch]);
        dt_t[((size_t)b * DI + ch) * SEQL + t0 + tx] = softplus_f(xv);
    }
}

// --------------------------- scan phase A ----------------------------------
__global__ void __launch_bounds__(256) scan_a_kernel(
    const float* __restrict__ ssm, const float* __restrict__ xconv_t,
    const float* __restrict__ dt_t, const float* __restrict__ A_log,
    float* __restrict__ Pout, float* __restrict__ hLout)
{
    __shared__ float sB[CLEN][DS];
    __shared__ float sxc[16][CLEN];
    __shared__ float sdt[16][CLEN];

    const int ch0 = blockIdx.x * 16;
    const int chunk = blockIdx.y;
    const int b = blockIdx.z;
    const int tid = threadIdx.x;
    const int chl = tid >> 4;
    const int n = tid & 15;
    const int ch = ch0 + chl;
    const int t0 = chunk * CLEN;

    for (int i = tid; i < CLEN * DS; i += 256) {
        const int t = i >> 4, nn = i & 15;
        sB[t][nn] = ssm[(size_t)(b * SEQL + t0 + t) * NXP + 1 + nn];
    }
    for (int i = tid; i < 16 * CLEN; i += 256) {
        const int r = i >> 6, t = i & 63;
        sxc[r][t] = xconv_t[((size_t)b * DI + ch0 + r) * SEQL + t0 + t];
        sdt[r][t] = dt_t[((size_t)b * DI + ch0 + r) * SEQL + t0 + t];
    }
    __syncthreads();

    const float An = -expf(A_log[ch * DS + n]);
    float h = 0.f, P = 1.f;
    #pragma unroll 4
    for (int t = 0; t < CLEN; ++t) {
        const float dtv = sdt[chl][t];
        const float ab = __expf(dtv * An);
        h = fmaf(ab, h, dtv * sxc[chl][t] * sB[t][n]);
        P *= ab;
    }
    const size_t idx = (((size_t)b * NCHUNK + chunk) * DI + ch) * DS + n;
    Pout[idx] = P;
    hLout[idx] = h;
}

// --------------------------- scan phase B ----------------------------------
__global__ void __launch_bounds__(256) scan_b_kernel(
    const float* __restrict__ P, const float* __restrict__ hL,
    float* __restrict__ h0)
{
    const int gid = blockIdx.x * 256 + threadIdx.x;
    const int b = gid / (DI * DS);
    const int r = gid - b * (DI * DS);
    float h = 0.f;
    #pragma unroll
    for (int c = 0; c < NCHUNK; ++c) {
        const size_t idx = ((size_t)(b * NCHUNK + c)) * (DI * DS) + r;
        h0[idx] = h;
        h = fmaf(P[idx], h, hL[idx]);
    }
}

// --------------------------- scan phase C + gate (bf16 y out) --------------
__global__ void __launch_bounds__(256) scan_c_kernel(
    const float* __restrict__ ssm, const float* __restrict__ xconv_t,
    const float* __restrict__ dt_t, const float* __restrict__ A_log,
    const float* __restrict__ Dp, const float* __restrict__ h0,
    const float* __restrict__ xz, __nv_bfloat16* __restrict__ y)
{
    __shared__ float sB[CLEN][DS];
    __shared__ float sC[CLEN][DS];
    __shared__ float sxc[16][CLEN];
    __shared__ float sdt[16][CLEN];
    __shared__ float sy[16][CLEN + 1];

    const int ch0 = blockIdx.x * 16;
    const int chunk = blockIdx.y;
    const int b = blockIdx.z;
    const int tid = threadIdx.x;
    const int chl = tid >> 4;
    const int n = tid & 15;
    const int ch = ch0 + chl;
    const int t0 = chunk * CLEN;

    for (int i = tid; i < CLEN * DS; i += 256) {
        const int t = i >> 4, nn = i & 15;
        const float* row = &ssm[(size_t)(b * SEQL + t0 + t) * NXP];
        sB[t][nn] = row[1 + nn];
        sC[t][nn] = row[1 + DS + nn];
    }
    for (int i = tid; i < 16 * CLEN; i += 256) {
        const int r = i >> 6, t = i & 63;
        sxc[r][t] = xconv_t[((size_t)b * DI + ch0 + r) * SEQL + t0 + t];
        sdt[r][t] = dt_t[((size_t)b * DI + ch0 + r) * SEQL + t0 + t];
    }
    __syncthreads();

    const float An = -expf(A_log[ch * DS + n]);
    const float Dch = Dp[ch];
    float h = h0[(((size_t)b * NCHUNK + chunk) * DI + ch) * DS + n];

    #pragma unroll 4
    for (int t = 0; t < CLEN; ++t) {
        const float dtv = sdt[chl][t];
        const float xcv = sxc[chl][t];
        const float ab = __expf(dtv * An);
        h = fmaf(ab, h, dtv * xcv * sB[t][n]);
        float p = h * sC[t][n];
        p += __shfl_xor_sync(0xffffffffu, p, 1);
        p += __shfl_xor_sync(0xffffffffu, p, 2);
        p += __shfl_xor_sync(0xffffffffu, p, 4);
        p += __shfl_xor_sync(0xffffffffu, p, 8);
        if (n == 0) sy[chl][t] = fmaf(xcv, Dch, p);
    }
    __syncthreads();

    for (int i = tid; i < CLEN * 16; i += 256) {
        const int t = i >> 4, c = i & 15;
        const int tok = b * SEQL + t0 + t;
        const float z = xz[(size_t)tok * (2 * DI) + DI + ch0 + c];
        y[(size_t)tok * DI + ch0 + c] = __float2bfloat16(sy[c][t] * silu_f(z));
    }
}

// ---------------------------------------------------------------------------
extern "C" void kernel_launch(void* const* d_in, const int* in_sizes, int n_in,
                              void* d_out, int out_size)
{
    const float* x      = (const float*)d_in[0];
    const float* W_in   = (const float*)d_in[1];
    const float* conv_w = (const float*)d_in[2];
    const float* conv_b = (const float*)d_in[3];
    const float* W_xproj= (const float*)d_in[4];
    const float* W_dt   = (const float*)d_in[5];
    const float* b_dt   = (const float*)d_in[6];
    const float* A_log  = (const float*)d_in[7];
    const float* Dp     = (const float*)d_in[8];
    const float* W_out  = (const float*)d_in[9];
    const float* norm_w = (const float*)d_in[10];
    float* out = (float*)d_out;

    __nv_bfloat16 *p_xn, *p_y, *p_WinT, *p_WoutT;
    float *p_xz, *p_xct, *p_ssm, *p_dtt, *p_xp, *p_P, *p_hL, *p_h0;
    cudaGetSymbolAddress((void**)&p_xn, g_xn);
    cudaGetSymbolAddress((void**)&p_y, g_y);
    cudaGetSymbolAddress((void**)&p_WinT, g_WinT);
    cudaGetSymbolAddress((void**)&p_WoutT, g_WoutT);
    cudaGetSymbolAddress((void**)&p_xz, g_xz);
    cudaGetSymbolAddress((void**)&p_xct, g_xconv_t);
    cudaGetSymbolAddress((void**)&p_ssm, g_ssm);
    cudaGetSymbolAddress((void**)&p_dtt, g_dt_t);
    cudaGetSymbolAddress((void**)&p_xp, g_xp);
    cudaGetSymbolAddress((void**)&p_P, g_P);
    cudaGetSymbolAddress((void**)&p_hL, g_hL);
    cudaGetSymbolAddress((void**)&p_h0, g_h0);

    static bool attr_done = false;
    if (!attr_done) {
        cudaFuncSetAttribute(gemm_bf16_kernel<false>,
                             cudaFuncAttributeMaxDynamicSharedMemorySize, GSMEMB);
        cudaFuncSetAttribute(gemm_bf16_kernel<true>,
                             cudaFuncAttributeMaxDynamicSharedMemorySize, GSMEMB);
        attr_done = true;
    }

    // 0) weight cvt+transpose to bf16 [N,K]
    cvtT_kernel<<<dim3((2 * DI) / 32, DM / 32), dim3(32, 8)>>>(W_in, p_WinT, DM, 2 * DI);
    cvtT_kernel<<<dim3(DM / 32, DI / 32), dim3(32, 8)>>>(W_out, p_WoutT, DI, DM);

    // 1) rmsnorm -> bf16 xn
    rmsnorm_kernel<<<TOK, 256>>>(x, norm_w, p_xn);

    // 2) xz = xn @ W_in  (bf16 tensor)
    gemm_bf16_kernel<false><<<dim3((2 * DI) / 128, TOK / 128), 256, GSMEMB>>>(
        p_xn, p_WinT, nullptr, p_xz, 2 * DI, DM);

    // 3) conv + silu -> [b][ch][t]
    conv_silu_t_kernel<<<dim3(DI / 32, SEQL / 32, 2), dim3(32, 8)>>>(
        p_xz, conv_w, conv_b, p_xct);

    // 4) xproj
    xproj_part_kernel<<<dim3(TOK / 128, KSPLIT), 128>>>(p_xct, W_xproj, p_xp);
    xproj_reduce_kernel<<<(NXP * TOK + 255) / 256, 256>>>(p_xp, p_ssm);

    // 5) dt precompute
    dt_t_kernel<<<dim3(DI / 64, SEQL / 32, 2), dim3(32, 8)>>>(
        p_ssm, W_dt, b_dt, p_dtt);

    // 6) 3-phase scan, gate fused into phase C (-> bf16 y)
    scan_a_kernel<<<dim3(DI / 16, NCHUNK, 2), 256>>>(
        p_ssm, p_xct, p_dtt, A_log, p_P, p_hL);
    scan_b_kernel<<<(2 * DI * DS) / 256, 256>>>(p_P, p_hL, p_h0);
    scan_c_kernel<<<dim3(DI / 16, NCHUNK, 2), 256>>>(
        p_ssm, p_xct, p_dtt, A_log, Dp, p_h0, p_xz, p_y);

    // 7) out = x + y @ W_out  (bf16 tensor)
    gemm_bf16_kernel<true><<<dim3(DM / 128, TOK / 128), 256, GSMEMB>>>(
        p_y, p_WoutT, x, out, DM, DI);
}

// round 16
// speedup vs baseline: 5.5098x; 1.0410x over previous
#include <cuda_runtime.h>
#include <cuda_bf16.h>
#include <math.h>
#include <stdint.h>

// ---------------------------------------------------------------------------
// MambaBlock: B=2, S=1024, D_MODEL=1024, D_INNER=2048, D_STATE=16, D_CONV=4
// Round 16: GEMM fragment loads via ldmatrix.x4 (24->6 instrs per k16-step),
// BK=64 ktiles (half the syncs), dt_t kernel removed (softplus computed in
// scan staging).
// ---------------------------------------------------------------------------

#define TOK 2048
#define DM  1024
#define DI  2048
#define DS  16
#define NXP 33
#define SEQL 1024
#define NCHUNK 16
#define CLEN 64
#define KSPLIT 32
#define KSEG (DI / KSPLIT)   // 64

__device__ __nv_bfloat16 g_xn[TOK * DM];
__device__ __nv_bfloat16 g_y[TOK * DI];
__device__ __nv_bfloat16 g_WinT[2 * DI * DM];   // [4096,1024] bf16
__device__ __nv_bfloat16 g_WoutT[DM * DI];      // [1024,2048] bf16
__device__ float g_xz[TOK * 2 * DI];
__device__ float g_xconv_t[TOK * DI];      // [b][ch][t]
__device__ float g_ssm[TOK * NXP];
__device__ float g_xp[KSPLIT * NXP * TOK];
__device__ float g_P[2 * NCHUNK * DI * DS];
__device__ float g_hL[2 * NCHUNK * DI * DS];
__device__ float g_h0[2 * NCHUNK * DI * DS];

// ------------------------------ helpers ------------------------------------
__device__ __forceinline__ uint32_t smem_u32(const void* p) {
    uint32_t a;
    asm("{ .reg .u64 t; cvta.to.shared.u64 t, %1; cvt.u32.u64 %0, t; }" : "=r"(a) : "l"(p));
    return a;
}
__device__ __forceinline__ void cp_async16(uint32_t dst, const void* src) {
    asm volatile("cp.async.cg.shared.global [%0], [%1], 16;" :: "r"(dst), "l"(src));
}
__device__ __forceinline__ void cp_commit() {
    asm volatile("cp.async.commit_group;");
}
__device__ __forceinline__ void ldsm_x4(uint32_t* r, uint32_t addr) {
    asm volatile("ldmatrix.sync.aligned.m8n8.x4.shared.b16 {%0,%1,%2,%3}, [%4];"
        : "=r"(r[0]), "=r"(r[1]), "=r"(r[2]), "=r"(r[3]) : "r"(addr));
}
__device__ __forceinline__ void mma_bf16(float* d, const uint32_t* a, const uint32_t* b) {
    asm volatile(
        "mma.sync.aligned.m16n8k16.row.col.f32.bf16.bf16.f32 "
        "{%0,%1,%2,%3}, {%4,%5,%6,%7}, {%8,%9}, {%0,%1,%2,%3};"
        : "+f"(d[0]), "+f"(d[1]), "+f"(d[2]), "+f"(d[3])
        : "r"(a[0]), "r"(a[1]), "r"(a[2]), "r"(a[3]), "r"(b[0]), "r"(b[1]));
}
__device__ __forceinline__ float softplus_f(float x) {
    return (x > 15.f) ? x : log1pf(expf(x));
}
__device__ __forceinline__ float silu_f(float x) {
    return x / (1.f + __expf(-x));
}

// ------------------------- mma.sync bf16 GEMM ------------------------------
// C[M,N] = A[M,K] @ Bt[N,K]^T (+ Rsd fp32).  BK=64, 3-stage cp.async,
// ldmatrix fragment loads.
#define SAb 72                      // bf16 row stride (144 B) for 64-k tile
#define TILEB (128 * SAb)           // 9216 bf16 per tile
#define GSMEMB (3 * 2 * TILEB * 2)  // 110592 bytes

template <bool RES>
__global__ void __launch_bounds__(256, 2) gemm_bf16_kernel(
    const __nv_bfloat16* __restrict__ A, const __nv_bfloat16* __restrict__ Bt,
    const float* __restrict__ Rsd, float* __restrict__ C,
    int Nout, int K)
{
    extern __shared__ __align__(16) __nv_bfloat16 smemb[];
    __nv_bfloat16* As = smemb;
    __nv_bfloat16* Bs = smemb + 3 * TILEB;
    const uint32_t as_u = smem_u32(As);
    const uint32_t bs_u = smem_u32(Bs);

    const int tid = threadIdx.x;
    const int wid = tid >> 5;
    const int lane = tid & 31;
    const int wr = wid & 3;
    const int wc = wid >> 2;
    const int g = lane >> 2;
    const int tig = lane & 3;

    const int row0 = blockIdx.y * 128;
    const int col0 = blockIdx.x * 128;
    const int KT = K >> 6;

    // ldmatrix per-lane address components
    const int a_row = (lane & 15);            // + rb
    const int a_kh = (lane >> 4) << 3;        // k half select
    const int b_nrow = ((lane >> 4) << 3) + (lane & 7);   // + nbase
    const int b_kh = ((lane >> 3) & 1) << 3;

    float acc[2][8][4];
    #pragma unroll
    for (int i = 0; i < 2; i++)
        #pragma unroll
        for (int j = 0; j < 8; j++)
            #pragma unroll
            for (int q = 0; q < 4; q++) acc[i][j][q] = 0.f;

    auto load_stage = [&](int i, int st) {
        const int k0 = i << 6;
        #pragma unroll
        for (int it = 0; it < 4; ++it) {
            const int s = it * 256 + tid;
            const int r = s >> 3;
            const int c = (s & 7) << 3;       // bf16 col
            cp_async16(as_u + (st * TILEB + r * SAb + c) * 2,
                       &A[(size_t)(row0 + r) * K + k0 + c]);
            cp_async16(bs_u + (st * TILEB + r * SAb + c) * 2,
                       &Bt[(size_t)(col0 + r) * K + k0 + c]);
        }
    };

    load_stage(0, 0); cp_commit();
    load_stage(1, 1); cp_commit();

    for (int i = 0; i < KT; ++i) {
        asm volatile("cp.async.wait_group 1;" ::: "memory");
        __syncthreads();
        if (i + 2 < KT) load_stage(i + 2, (i + 2) % 3);
        cp_commit();

        const uint32_t abase = as_u + ((i % 3) * TILEB) * 2;
        const uint32_t bbase = bs_u + ((i % 3) * TILEB) * 2;
        #pragma unroll
        for (int ks = 0; ks < 4; ++ks) {
            const int kk = (ks << 4);
            uint32_t afr[2][4];
            #pragma unroll
            for (int mt = 0; mt < 2; ++mt) {
                const int rb = wr * 32 + mt * 16;
                ldsm_x4(afr[mt], abase + ((rb + a_row) * SAb + kk + a_kh) * 2);
            }
            uint32_t bfr[4][4];
            #pragma unroll
            for (int p = 0; p < 4; ++p) {
                const int nb = wc * 64 + p * 16;
                ldsm_x4(bfr[p], bbase + ((nb + b_nrow) * SAb + kk + b_kh) * 2);
            }
            #pragma unroll
            for (int mt = 0; mt < 2; ++mt)
                #pragma unroll
                for (int nt = 0; nt < 8; ++nt)
                    mma_bf16(acc[mt][nt], afr[mt], &bfr[nt >> 1][(nt & 1) * 2]);
        }
    }

    #pragma unroll
    for (int mt = 0; mt < 2; ++mt) {
        const int r0 = row0 + wr * 32 + mt * 16 + g;
        #pragma unroll
        for (int nt = 0; nt < 8; ++nt) {
            const int c = col0 + wc * 64 + nt * 8 + tig * 2;
            float2 v0 = make_float2(acc[mt][nt][0], acc[mt][nt][1]);
            float2 v1 = make_float2(acc[mt][nt][2], acc[mt][nt][3]);
            if (RES) {
                float2 r0v = *reinterpret_cast<const float2*>(&Rsd[(size_t)r0 * Nout + c]);
                float2 r1v = *reinterpret_cast<const float2*>(&Rsd[(size_t)(r0 + 8) * Nout + c]);
                v0.x += r0v.x; v0.y += r0v.y;
                v1.x += r1v.x; v1.y += r1v.y;
            }
            *reinterpret_cast<float2*>(&C[(size_t)r0 * Nout + c]) = v0;
            *reinterpret_cast<float2*>(&C[(size_t)(r0 + 8) * Nout + c]) = v1;
        }
    }
}

// ---------------- weight convert + transpose (fp32[R,C] -> bf16[C,R]) ------
__global__ void __launch_bounds__(256) cvtT_kernel(
    const float* __restrict__ in, __nv_bfloat16* __restrict__ out, int R, int Ccols)
{
    __shared__ float tile[32][33];
    const int c0 = blockIdx.x * 32, r0 = blockIdx.y * 32;
    const int x = threadIdx.x, y = threadIdx.y;
    #pragma unroll
    for (int j = 0; j < 32; j += 8)
        tile[y + j][x] = in[(size_t)(r0 + y + j) * Ccols + c0 + x];
    __syncthreads();
    #pragma unroll
    for (int j = 0; j < 32; j += 8)
        out[(size_t)(c0 + y + j) * R + r0 + x] = __float2bfloat16(tile[x][y + j]);
}

// ------------------------------ rmsnorm (bf16 out) -------------------------
__global__ void __launch_bounds__(256) rmsnorm_kernel(
    const float* __restrict__ x, const float* __restrict__ w,
    __nv_bfloat16* __restrict__ xn)
{
    const int token = blockIdx.x;
    const int tid = threadIdx.x;
    const float4* x4 = reinterpret_cast<const float4*>(x + (size_t)token * DM);
    float4 v = x4[tid];
    float s = v.x * v.x + v.y * v.y + v.z * v.z + v.w * v.w;
    __shared__ float red[8];
    #pragma unroll
    for (int o = 16; o; o >>= 1) s += __shfl_xor_sync(0xffffffffu, s, o);
    if ((tid & 31) == 0) red[tid >> 5] = s;
    __syncthreads();
    if (tid < 32) {
        float t = (tid < 8) ? red[tid] : 0.f;
        #pragma unroll
        for (int o = 4; o; o >>= 1) t += __shfl_xor_sync(0xffffffffu, t, o);
        if (tid == 0) red[0] = t;
    }
    __syncthreads();
    const float ms = red[0] * (1.f / (float)DM);
    const float r = rsqrtf(ms + 1.1920928955078125e-07f);
    const float4* w4 = reinterpret_cast<const float4*>(w);
    float4 wv = w4[tid];
    __nv_bfloat162* o2 = reinterpret_cast<__nv_bfloat162*>(xn + (size_t)token * DM) + tid * 2;
    o2[0] = __floats2bfloat162_rn(v.x * r * wv.x, v.y * r * wv.y);
    o2[1] = __floats2bfloat162_rn(v.z * r * wv.z, v.w * r * wv.w);
}

// ------------- causal depthwise conv + silu, transposed output -------------
__global__ void __launch_bounds__(256) conv_silu_t_kernel(
    const float* __restrict__ xz, const float* __restrict__ cw,
    const float* __restrict__ cb, float* __restrict__ xconv_t)
{
    __shared__ float tile[35][33];
    const int ch0 = blockIdx.x * 32;
    const int t0 = blockIdx.y * 32;
    const int b = blockIdx.z;
    const int tx = threadIdx.x, ty = threadIdx.y;

    for (int j = ty; j < 35; j += 8) {
        const int tg = t0 + j - 3;
        tile[j][tx] = (tg >= 0) ? xz[(size_t)(b * SEQL + tg) * (2 * DI) + ch0 + tx] : 0.f;
    }
    __syncthreads();

    #pragma unroll
    for (int q = 0; q < 4; ++q) {
        const int chl = ty + q * 8;
        const int ch = ch0 + chl;
        float acc = cb[ch];
        #pragma unroll
        for (int k = 0; k < 4; ++k)
            acc = fmaf(tile[tx + k][chl], cw[ch * 4 + k], acc);
        xconv_t[((size_t)b * DI + ch) * SEQL + t0 + tx] = silu_f(acc);
    }
}

// ---------------------- xproj partials (32-way k-split) --------------------
__global__ void __launch_bounds__(128) xproj_part_kernel(
    const float* __restrict__ xconv_t, const float* __restrict__ W,
    float* __restrict__ part)
{
    __shared__ float Wbuf[KSEG][NXP];
    const int tok = blockIdx.x * 128 + threadIdx.x;
    const int b = tok >> 10;
    const int t = tok & (SEQL - 1);
    const int ks = blockIdx.y;
    const int kbase = ks * KSEG;

    for (int i = threadIdx.x; i < KSEG * NXP; i += 128) {
        const int kr = i / NXP, c = i - kr * NXP;
        Wbuf[kr][c] = W[(size_t)(kbase + kr) * NXP + c];
    }
    __syncthreads();

    float acc[NXP];
    #pragma unroll
    for (int c = 0; c < NXP; ++c) acc[c] = 0.f;

    #pragma unroll 4
    for (int kr = 0; kr < KSEG; ++kr) {
        const float xv = xconv_t[((size_t)b * DI + kbase + kr) * SEQL + t];
        #pragma unroll
        for (int c = 0; c < NXP; ++c)
            acc[c] = fmaf(xv, Wbuf[kr][c], acc[c]);
    }
    #pragma unroll
    for (int c = 0; c < NXP; ++c)
        part[((size_t)ks * NXP + c) * TOK + tok] = acc[c];
}

__global__ void __launch_bounds__(256) xproj_reduce_kernel(
    const float* __restrict__ part, float* __restrict__ ssm)
{
    const int idx = blockIdx.x * 256 + threadIdx.x;
    if (idx >= NXP * TOK) return;
    const int c = idx / TOK;
    const int tok = idx - c * TOK;
    float s = 0.f;
    #pragma unroll
    for (int ks = 0; ks < KSPLIT; ++ks)
        s += part[((size_t)ks * NXP + c) * TOK + tok];
    ssm[(size_t)tok * NXP + c] = s;
}

// --------------------------- scan phase A ----------------------------------
// Block 256 = 16 ch x 16 n, one chunk; softplus(dt) computed in staging.
__global__ void __launch_bounds__(256) scan_a_kernel(
    const float* __restrict__ ssm, const float* __restrict__ xconv_t,
    const float* __restrict__ A_log, const float* __restrict__ W_dt,
    const float* __restrict__ b_dt, float* __restrict__ Pout,
    float* __restrict__ hLout)
{
    __shared__ float sB[CLEN][DS];
    __shared__ float sxc[16][CLEN];
    __shared__ float sdt[16][CLEN];
    __shared__ float sdtraw[CLEN];
    __shared__ float swdt[16], sbdt[16];

    const int ch0 = blockIdx.x * 16;
    const int chunk = blockIdx.y;
    const int b = blockIdx.z;
    const int tid = threadIdx.x;
    const int chl = tid >> 4;
    const int n = tid & 15;
    const int ch = ch0 + chl;
    const int t0 = chunk * CLEN;

    for (int i = tid; i < CLEN * DS; i += 256) {
        const int t = i >> 4, nn = i & 15;
        sB[t][nn] = ssm[(size_t)(b * SEQL + t0 + t) * NXP + 1 + nn];
    }
    for (int i = tid; i < 16 * CLEN; i += 256) {
        const int r = i >> 6, t = i & 63;
        sxc[r][t] = xconv_t[((size_t)b * DI + ch0 + r) * SEQL + t0 + t];
    }
    if (tid < CLEN) sdtraw[tid] = ssm[(size_t)(b * SEQL + t0 + tid) * NXP];
    if (tid >= 224 && tid < 240) {
        swdt[tid - 224] = W_dt[ch0 + tid - 224];
        sbdt[tid - 224] = b_dt[ch0 + tid - 224];
    }
    __syncthreads();
    for (int i = tid; i < 16 * CLEN; i += 256) {
        const int r = i >> 6, t = i & 63;
        sdt[r][t] = softplus_f(fmaf(sdtraw[t], swdt[r], sbdt[r]));
    }
    __syncthreads();

    const float An = -expf(A_log[ch * DS + n]);
    float h = 0.f, P = 1.f;
    #pragma unroll 4
    for (int t = 0; t < CLEN; ++t) {
        const float dtv = sdt[chl][t];
        const float ab = __expf(dtv * An);
        h = fmaf(ab, h, dtv * sxc[chl][t] * sB[t][n]);
        P *= ab;
    }
    const size_t idx = (((size_t)b * NCHUNK + chunk) * DI + ch) * DS + n;
    Pout[idx] = P;
    hLout[idx] = h;
}

// --------------------------- scan phase B ----------------------------------
__global__ void __launch_bounds__(256) scan_b_kernel(
    const float* __restrict__ P, const float* __restrict__ hL,
    float* __restrict__ h0)
{
    const int gid = blockIdx.x * 256 + threadIdx.x;
    const int b = gid / (DI * DS);
    const int r = gid - b * (DI * DS);
    float h = 0.f;
    #pragma unroll
    for (int c = 0; c < NCHUNK; ++c) {
        const size_t idx = ((size_t)(b * NCHUNK + c)) * (DI * DS) + r;
        h0[idx] = h;
        h = fmaf(P[idx], h, hL[idx]);
    }
}

// --------------------------- scan phase C + gate (bf16 y out) --------------
__global__ void __launch_bounds__(256) scan_c_kernel(
    const float* __restrict__ ssm, const float* __restrict__ xconv_t,
    const float* __restrict__ A_log, const float* __restrict__ W_dt,
    const float* __restrict__ b_dt, const float* __restrict__ Dp,
    const float* __restrict__ h0, const float* __restrict__ xz,
    __nv_bfloat16* __restrict__ y)
{
    __shared__ float sB[CLEN][DS];
    __shared__ float sC[CLEN][DS];
    __shared__ float sxc[16][CLEN];
    __shared__ float sdt[16][CLEN];
    __shared__ float sy[16][CLEN + 1];
    __shared__ float sdtraw[CLEN];
    __shared__ float swdt[16], sbdt[16];

    const int ch0 = blockIdx.x * 16;
    const int chunk = blockIdx.y;
    const int b = blockIdx.z;
    const int tid = threadIdx.x;
    const int chl = tid >> 4;
    const int n = tid & 15;
    const int ch = ch0 + chl;
    const int t0 = chunk * CLEN;

    for (int i = tid; i < CLEN * DS; i += 256) {
        const int t = i >> 4, nn = i & 15;
        const float* row = &ssm[(size_t)(b * SEQL + t0 + t) * NXP];
        sB[t][nn] = row[1 + nn];
        sC[t][nn] = row[1 + DS + nn];
    }
    for (int i = tid; i < 16 * CLEN; i += 256) {
        const int r = i >> 6, t = i & 63;
        sxc[r][t] = xconv_t[((size_t)b * DI + ch0 + r) * SEQL + t0 + t];
    }
    if (tid < CLEN) sdtraw[tid] = ssm[(size_t)(b * SEQL + t0 + tid) * NXP];
    if (tid >= 224 && tid < 240) {
        swdt[tid - 224] = W_dt[ch0 + tid - 224];
        sbdt[tid - 224] = b_dt[ch0 + tid - 224];
    }
    __syncthreads();
    for (int i = tid; i < 16 * CLEN; i += 256) {
        const int r = i >> 6, t = i & 63;
        sdt[r][t] = softplus_f(fmaf(sdtraw[t], swdt[r], sbdt[r]));
    }
    __syncthreads();

    const float An = -expf(A_log[ch * DS + n]);
    const float Dch = Dp[ch];
    float h = h0[(((size_t)b * NCHUNK + chunk) * DI + ch) * DS + n];

    #pragma unroll 4
    for (int t = 0; t < CLEN; ++t) {
        const float dtv = sdt[chl][t];
        const float xcv = sxc[chl][t];
        const float ab = __expf(dtv * An);
        h = fmaf(ab, h, dtv * xcv * sB[t][n]);
        float p = h * sC[t][n];
        p += __shfl_xor_sync(0xffffffffu, p, 1);
        p += __shfl_xor_sync(0xffffffffu, p, 2);
        p += __shfl_xor_sync(0xffffffffu, p, 4);
        p += __shfl_xor_sync(0xffffffffu, p, 8);
        if (n == 0) sy[chl][t] = fmaf(xcv, Dch, p);
    }
    __syncthreads();

    for (int i = tid; i < CLEN * 16; i += 256) {
        const int t = i >> 4, c = i & 15;
        const int tok = b * SEQL + t0 + t;
        const float z = xz[(size_t)tok * (2 * DI) + DI + ch0 + c];
        y[(size_t)tok * DI + ch0 + c] = __float2bfloat16(sy[c][t] * silu_f(z));
    }
}

// ---------------------------------------------------------------------------
extern "C" void kernel_launch(void* const* d_in, const int* in_sizes, int n_in,
                              void* d_out, int out_size)
{
    const float* x      = (const float*)d_in[0];
    const float* W_in   = (const float*)d_in[1];
    const float* conv_w = (const float*)d_in[2];
    const float* conv_b = (const float*)d_in[3];
    const float* W_xproj= (const float*)d_in[4];
    const float* W_dt   = (const float*)d_in[5];
    const float* b_dt   = (const float*)d_in[6];
    const float* A_log  = (const float*)d_in[7];
    const float* Dp     = (const float*)d_in[8];
    const float* W_out  = (const float*)d_in[9];
    const float* norm_w = (const float*)d_in[10];
    float* out = (float*)d_out;

    __nv_bfloat16 *p_xn, *p_y, *p_WinT, *p_WoutT;
    float *p_xz, *p_xct, *p_ssm, *p_xp, *p_P, *p_hL, *p_h0;
    cudaGetSymbolAddress((void**)&p_xn, g_xn);
    cudaGetSymbolAddress((void**)&p_y, g_y);
    cudaGetSymbolAddress((void**)&p_WinT, g_WinT);
    cudaGetSymbolAddress((void**)&p_WoutT, g_WoutT);
    cudaGetSymbolAddress((void**)&p_xz, g_xz);
    cudaGetSymbolAddress((void**)&p_xct, g_xconv_t);
    cudaGetSymbolAddress((void**)&p_ssm, g_ssm);
    cudaGetSymbolAddress((void**)&p_xp, g_xp);
    cudaGetSymbolAddress((void**)&p_P, g_P);
    cudaGetSymbolAddress((void**)&p_hL, g_hL);
    cudaGetSymbolAddress((void**)&p_h0, g_h0);

    static bool attr_done = false;
    if (!attr_done) {
        cudaFuncSetAttribute(gemm_bf16_kernel<false>,
                             cudaFuncAttributeMaxDynamicSharedMemorySize, GSMEMB);
        cudaFuncSetAttribute(gemm_bf16_kernel<true>,
                             cudaFuncAttributeMaxDynamicSharedMemorySize, GSMEMB);
        attr_done = true;
    }

    // 0) weight cvt+transpose to bf16 [N,K]
    cvtT_kernel<<<dim3((2 * DI) / 32, DM / 32), dim3(32, 8)>>>(W_in, p_WinT, DM, 2 * DI);
    cvtT_kernel<<<dim3(DM / 32, DI / 32), dim3(32, 8)>>>(W_out, p_WoutT, DI, DM);

    // 1) rmsnorm -> bf16 xn
    rmsnorm_kernel<<<TOK, 256>>>(x, norm_w, p_xn);

    // 2) xz = xn @ W_in
    gemm_bf16_kernel<false><<<dim3((2 * DI) / 128, TOK / 128), 256, GSMEMB>>>(
        p_xn, p_WinT, nullptr, p_xz, 2 * DI, DM);

    // 3) conv + silu -> [b][ch][t]
    conv_silu_t_kernel<<<dim3(DI / 32, SEQL / 32, 2), dim3(32, 8)>>>(
        p_xz, conv_w, conv_b, p_xct);

    // 4) xproj
    xproj_part_kernel<<<dim3(TOK / 128, KSPLIT), 128>>>(p_xct, W_xproj, p_xp);
    xproj_reduce_kernel<<<(NXP * TOK + 255) / 256, 256>>>(p_xp, p_ssm);

    // 5) 3-phase scan (softplus in staging), gate fused into phase C
    scan_a_kernel<<<dim3(DI / 16, NCHUNK, 2), 256>>>(
        p_ssm, p_xct, A_log, W_dt, b_dt, p_P, p_hL);
    scan_b_kernel<<<(2 * DI * DS) / 256, 256>>>(p_P, p_hL, p_h0);
    scan_c_kernel<<<dim3(DI / 16, NCHUNK, 2), 256>>>(
        p_ssm, p_xct, A_log, W_dt, b_dt, Dp, p_h0, p_xz, p_y);

    // 6) out = x + y @ W_out
    gemm_bf16_kernel<true><<<dim3(DM / 128, TOK / 128), 256, GSMEMB>>>(
        p_y, p_WoutT, x, out, DM, DI);
}